// round 13
// baseline (speedup 1.0000x reference)
#include <cuda_runtime.h>
#include <cuda_bf16.h>
#include <math.h>
#include <stdint.h>

// Problem constants: B=16, C=256, H=W=32
#define PNUM 16384
#define CNUM 256
#define CLIP1 0.9999999f
#define MAXN  0.99999f
#define EPSF  1e-15f

#define NPOS 36
#define NTIL 1024
#define STAGE_BYTES 24576u       // Ahi 8K + Alo 8K + Bhi 4K + Blo 4K
#define CONV_SMEM (3*24576)      // 72 KB -> 3 CTAs/SM

// ---------------- device scratch ----------------
__device__ __align__(16) float g_v [PNUM*CNUM];
__device__ __align__(16) __nv_bfloat16 g_Vhi[NPOS*NTIL*CNUM];
__device__ __align__(16) __nv_bfloat16 g_Vlo[NPOS*NTIL*CNUM];
__device__ __align__(16) __nv_bfloat16 g_uhi1[NPOS*CNUM*CNUM];
__device__ __align__(16) __nv_bfloat16 g_ulo1[NPOS*CNUM*CNUM];
__device__ __align__(16) __nv_bfloat16 g_uhi2[NPOS*CNUM*CNUM];
__device__ __align__(16) __nv_bfloat16 g_ulo2[NPOS*CNUM*CNUM];
__device__ __align__(16) float g_m [NPOS*NTIL*CNUM];
__device__ __align__(16) float g_h [PNUM*CNUM];   // NORMALIZED h (post FC)
__device__ __align__(16) float g_xl[PNUM*CNUM];
__device__ float g_q2[PNUM];
__device__ float g_zn[512];
__device__ float g_pm [NTIL*CNUM];
__device__ float g_pm2[8*CNUM];
__device__ float g_pd[NTIL];
__device__ float g_pv[512];
__device__ float g_mu[CNUM];
__device__ float g_sc[8];
__device__ int   g_ctr  = 0;
__device__ int   g_ctr2 = 0;

// ---------------- PTX helpers ----------------
__device__ __forceinline__ uint32_t smem_u32(const void* p) {
    uint32_t a;
    asm("{ .reg .u64 t; cvta.to.shared.u64 t, %1; cvt.u32.u64 %0, t; }" : "=r"(a) : "l"(p));
    return a;
}
__device__ __forceinline__ void cpa16(uint32_t dst, const void* src) {
    asm volatile("cp.async.cg.shared.global [%0], [%1], 16;" :: "r"(dst), "l"(src) : "memory");
}
__device__ __forceinline__ void cp_commit() {
    asm volatile("cp.async.commit_group;" ::: "memory");
}
template<int N>
__device__ __forceinline__ void cp_wait() {
    asm volatile("cp.async.wait_group %0;" :: "n"(N) : "memory");
}
__device__ __forceinline__ void ldsm4(uint32_t* r, uint32_t addr) {
    asm volatile("ldmatrix.sync.aligned.m8n8.x4.shared.b16 {%0,%1,%2,%3}, [%4];"
        : "=r"(r[0]), "=r"(r[1]), "=r"(r[2]), "=r"(r[3]) : "r"(addr));
}
__device__ __forceinline__ void mma16816(float* d, const uint32_t* a, const uint32_t* b) {
    asm volatile("mma.sync.aligned.m16n8k16.row.col.f32.bf16.bf16.f32 "
        "{%0,%1,%2,%3}, {%4,%5,%6,%7}, {%8,%9}, {%0,%1,%2,%3};"
        : "+f"(d[0]), "+f"(d[1]), "+f"(d[2]), "+f"(d[3])
        : "r"(a[0]), "r"(a[1]), "r"(a[2]), "r"(a[3]), "r"(b[0]), "r"(b[1]));
}
__device__ __forceinline__ uint32_t swz(int r, int c) {
    return (uint32_t)(((r >> 1) << 7) | (((((r & 1) << 2) | c) ^ ((r >> 1) & 7)) << 4));
}

// ---------------- reductions ----------------
__device__ __forceinline__ float warpSum(float v) {
#pragma unroll
    for (int o = 16; o > 0; o >>= 1) v += __shfl_xor_sync(0xffffffffu, v, o);
    return v;
}
template<int K>
__device__ __forceinline__ void blockReduceK(float* v, float* sbuf) {
    int tid = threadIdx.x, lane = tid & 31, wid = tid >> 5;
#pragma unroll
    for (int i = 0; i < K; i++) {
        float x = v[i];
#pragma unroll
        for (int o = 16; o > 0; o >>= 1) x += __shfl_down_sync(0xffffffffu, x, o);
        if (lane == 0) sbuf[i*8 + wid] = x;
    }
    __syncthreads();
    if (tid == 0) {
#pragma unroll
        for (int i = 0; i < K; i++) {
            float s = sbuf[i*8];
            for (int w = 1; w < 8; w++) s += sbuf[i*8 + w];
            sbuf[i*8] = s;
        }
    }
    __syncthreads();
#pragma unroll
    for (int i = 0; i < K; i++) v[i] = sbuf[i*8];
    __syncthreads();
}

// ---------------- Winograd transforms ----------------
__device__ __forceinline__ void bt6(const float* in, float* out) {
    out[0] =  4.f*in[0] - 5.f*in[2] + in[4];
    out[1] = -4.f*in[1] - 4.f*in[2] + in[3] + in[4];
    out[2] =  4.f*in[1] - 4.f*in[2] - in[3] + in[4];
    out[3] = -2.f*in[1] -     in[2] + 2.f*in[3] + in[4];
    out[4] =  2.f*in[1] -     in[2] - 2.f*in[3] + in[4];
    out[5] =  4.f*in[1] - 5.f*in[3] + in[5];
}
__device__ __forceinline__ void g6(const float* in, float* out) {
    out[0] = 0.25f*in[0];
    out[1] = -(in[0] + in[1] + in[2]) * (1.f/6.f);
    out[2] = (-in[0] + in[1] - in[2]) * (1.f/6.f);
    out[3] = in[0]*(1.f/24.f) + in[1]*(1.f/12.f) + in[2]*(1.f/6.f);
    out[4] = in[0]*(1.f/24.f) - in[1]*(1.f/12.f) + in[2]*(1.f/6.f);
    out[5] = in[2];
}
__device__ __forceinline__ void at6(const float* in, float* out) {
    out[0] = in[0] + in[1] + in[2] + in[3] + in[4];
    out[1] = in[1] - in[2] + 2.f*(in[3] - in[4]);
    out[2] = in[1] + in[2] + 4.f*(in[3] + in[4]);
    out[3] = in[1] - in[2] + 8.f*(in[3] - in[4]) + in[5];
}

// ---------------- U = G z G^T (+ fused z column norms), both weight sets ----------------
__global__ void wino_u(const float* __restrict__ z1, const float* __restrict__ z2) {
    __shared__ float sb[8];
    const float* z = blockIdx.y ? z2 : z1;
    __nv_bfloat16* uh = blockIdx.y ? g_uhi2 : g_uhi1;
    __nv_bfloat16* ul = blockIdx.y ? g_ulo2 : g_ulo1;
    int co = blockIdx.x, ci = threadIdx.x;
    float g[3][3];
    float nsum = 0.f;
#pragma unroll
    for (int i = 0; i < 3; i++)
#pragma unroll
        for (int j = 0; j < 3; j++) {
            float w = z[(size_t)((i*3 + j)*256 + ci)*256 + co];
            g[i][j] = w;
            nsum += w*w;
        }
    float r1[1] = { nsum };
    blockReduceK<1>(r1, sb);
    if (ci == 0) g_zn[blockIdx.y*256 + co] = sqrtf(fmaxf(r1[0], EPSF));

    float t[6][3];
#pragma unroll
    for (int j = 0; j < 3; j++) {
        float in[3] = { g[0][j], g[1][j], g[2][j] };
        float out[6];
        g6(in, out);
#pragma unroll
        for (int a = 0; a < 6; a++) t[a][j] = out[a];
    }
#pragma unroll
    for (int a = 0; a < 6; a++) {
        float out[6];
        g6(t[a], out);
#pragma unroll
        for (int b = 0; b < 6; b++) {
            float u = out[b];
            __nv_bfloat16 hi = __float2bfloat16(u);
            size_t idx = ((size_t)((a*6 + b)*256 + co))*256 + ci;
            uh[idx] = hi;
            ul[idx] = __float2bfloat16(u - __bfloat162float(hi));
        }
    }
}

// ---------------- V = B^T d B per tile ----------------
__global__ void wino_in() {
    int t = blockIdx.x, ci = threadIdx.x;
    int b = t >> 6, tr = (t >> 3) & 7, tc = t & 7;
    int base = b << 10;
    float d[6][6];
#pragma unroll
    for (int y = 0; y < 6; y++) {
        int iy = 4*tr - 1 + y;
#pragma unroll
        for (int x = 0; x < 6; x++) {
            int ix = 4*tc - 1 + x;
            bool ok = ((unsigned)iy < 32u) && ((unsigned)ix < 32u);
            d[y][x] = ok ? g_v[(size_t)(base + iy*32 + ix)*256 + ci] : 0.f;
        }
    }
    float e[6][6];
#pragma unroll
    for (int x = 0; x < 6; x++) {
        float in[6] = { d[0][x], d[1][x], d[2][x], d[3][x], d[4][x], d[5][x] };
        float out[6];
        bt6(in, out);
#pragma unroll
        for (int a = 0; a < 6; a++) e[a][x] = out[a];
    }
#pragma unroll
    for (int a = 0; a < 6; a++) {
        float out[6];
        bt6(e[a], out);
#pragma unroll
        for (int bb = 0; bb < 6; bb++) {
            float v = out[bb];
            __nv_bfloat16 hi = __float2bfloat16(v);
            size_t idx = ((size_t)((a*6 + bb)*NTIL + t))*256 + ci;
            g_Vhi[idx] = hi;
            g_Vlo[idx] = __float2bfloat16(v - __bfloat162float(hi));
        }
    }
}

// ---------------- batched Winograd GEMM: 3 positions per CTA, single wave ----------------
// grid (8, 4, 12). CTA 128x64, warp 32x32, 3 CTAs/SM. Accumulators flush to
// g_m at each 8-chunk position boundary; cp.async ring runs continuously.
__global__ void __launch_bounds__(256, 3) wino_gemm(int which) {
    extern __shared__ __align__(16) char dsm[];
    uint32_t sbase = smem_u32(dsm);

    const __nv_bfloat16* Bh = which ? g_uhi2 : g_uhi1;
    const __nv_bfloat16* Bl = which ? g_ulo2 : g_ulo1;
    int t0  = blockIdx.x << 7;
    int nq  = blockIdx.y;
    int pos0 = blockIdx.z * 3;

    int tid = threadIdx.x, wid = tid >> 5, l = tid & 31;

    int c4 = tid & 3;
    int r0 = tid >> 2;
    uint32_t ph0 = swz(r0, c4), ph1 = swz(r0 + 64, c4);
    size_t a0 = (size_t)r0*256 + c4*8, a1 = (size_t)(r0 + 64)*256 + c4*8;
    const __nv_bfloat16* Ahi_b = g_Vhi + ((size_t)pos0*NTIL + t0)*256;
    const __nv_bfloat16* Alo_b = g_Vlo + ((size_t)pos0*NTIL + t0)*256;
    const __nv_bfloat16* Bhi_b = Bh + ((size_t)pos0*256 + nq*64)*256;
    const __nv_bfloat16* Blo_b = Bl + ((size_t)pos0*256 + nq*64)*256;

    int m0 = (wid & 3) << 5;
    int n0w = (wid >> 2) << 5;
    int mi = l >> 3;
    int rA = m0 + ((mi & 1) << 3) + (l & 7);
    uint32_t qA0 = swz(rA, mi >> 1);
    int rB = n0w + (((mi >> 1) & 1) << 3) + (l & 7);
    uint32_t qB0 = swz(rB, mi & 1);
    int row0 = m0 + (l >> 2);
    int col0 = n0w + ((l & 3) << 1);

    float acc[2][4][4];
#pragma unroll
    for (int i = 0; i < 2; i++)
#pragma unroll
        for (int j = 0; j < 4; j++)
#pragma unroll
            for (int k = 0; k < 4; k++) acc[i][j][k] = 0.f;

    auto load_chunk = [&](int kcg, int stage) {
        int pp = kcg >> 3;                           // 0..2 within this CTA
        size_t coff = (size_t)((kcg & 7) << 5);
        size_t ao = (size_t)pp*NTIL*256 + coff;
        size_t bo = (size_t)pp*256*256 + coff;
        uint32_t st = sbase + (uint32_t)stage*STAGE_BYTES;
        cpa16(st + ph0,         Ahi_b + ao + a0);
        cpa16(st + 8192 + ph0,  Alo_b + ao + a0);
        cpa16(st + ph1,         Ahi_b + ao + a1);
        cpa16(st + 8192 + ph1,  Alo_b + ao + a1);
        cpa16(st + 16384 + ph0, Bhi_b + bo + a0);
        cpa16(st + 20480 + ph0, Blo_b + bo + a0);
        cp_commit();
    };

    load_chunk(0, 0);
    load_chunk(1, 1);

    for (int kc = 0; kc < 24; kc++) {
        int stage = kc % 3;
        if (kc < 22) cp_wait<1>(); else cp_wait<0>();
        __syncthreads();
        if (kc + 2 < 24) load_chunk(kc + 2, (kc + 2) % 3);

        uint32_t st = sbase + (uint32_t)stage*STAGE_BYTES;
        uint32_t Ahi = st, Alo = st + 8192, Bhi = st + 16384, Blo = st + 20480;
#pragma unroll
        for (int ks = 0; ks < 2; ks++) {
            uint32_t kx = (uint32_t)(ks << 5);
            uint32_t qa = qA0 ^ kx, qb = qB0 ^ kx;
            uint32_t ah[8], al[8], bbv[8];
            ldsm4(bbv,     Bhi + qb);
            ldsm4(bbv + 4, Bhi + qb + 1024);
            ldsm4(ah,     Ahi + qa);
            ldsm4(ah + 4, Ahi + qa + 1024);
            ldsm4(al,     Alo + qa);
            ldsm4(al + 4, Alo + qa + 1024);
#pragma unroll
            for (int nf = 0; nf < 4; nf++) {
                const uint32_t* bp = bbv + nf*2;
                mma16816(acc[0][nf], ah,     bp);
                mma16816(acc[1][nf], ah + 4, bp);
            }
#pragma unroll
            for (int nf = 0; nf < 4; nf++) {
                const uint32_t* bp = bbv + nf*2;
                mma16816(acc[0][nf], al,     bp);
                mma16816(acc[1][nf], al + 4, bp);
            }
            ldsm4(bbv,     Blo + qb);
            ldsm4(bbv + 4, Blo + qb + 1024);
#pragma unroll
            for (int nf = 0; nf < 4; nf++) {
                const uint32_t* bp = bbv + nf*2;
                mma16816(acc[0][nf], ah,     bp);
                mma16816(acc[1][nf], ah + 4, bp);
            }
        }

        if ((kc & 7) == 7) {
            // position boundary: flush accumulators to g_m, reset
            int pp = kc >> 3;
            float* gm = g_m + ((size_t)(pos0 + pp)*NTIL + t0)*256 + nq*64;
#pragma unroll
            for (int mf = 0; mf < 2; mf++)
#pragma unroll
                for (int hf = 0; hf < 2; hf++) {
                    int r = row0 + mf*16 + hf*8;
                    float* rowp = gm + (size_t)r*256;
#pragma unroll
                    for (int nf = 0; nf < 4; nf++)
                        *(float2*)(rowp + col0 + nf*8) =
                            make_float2(acc[mf][nf][hf*2], acc[mf][nf][hf*2 + 1]);
                }
#pragma unroll
            for (int i = 0; i < 2; i++)
#pragma unroll
                for (int j = 0; j < 4; j++)
#pragma unroll
                    for (int k = 0; k < 4; k++) acc[i][j][k] = 0.f;
        }
    }
}

// ---------------- pre2 (+ fused xT) ----------------
__global__ void pre2_kernel(const float* __restrict__ x, float scale) {
    __shared__ float sx[256][33];
    int tid = threadIdx.x, lane = tid & 31, w8 = tid >> 5;
    int p0 = blockIdx.x * 32;
    int b = p0 >> 10, hw0 = p0 & 1023;
#pragma unroll 8
    for (int i = 0; i < 32; i++) {
        int c = i*8 + w8;
        sx[c][lane] = x[(size_t)(b*256 + c)*1024 + hw0 + lane];
    }
    __syncthreads();
#pragma unroll 8
    for (int pl = 0; pl < 32; pl++)
        g_xl[(size_t)(p0 + pl)*256 + tid] = sx[tid][pl];
#pragma unroll
    for (int pp = 0; pp < 4; pp++) {
        int pl = w8*4 + pp;
        int p = p0 + pl;
        float xv[8];
#pragma unroll
        for (int i = 0; i < 8; i++) xv[i] = sx[lane*8 + i][pl];
        float q = 0.f;
#pragma unroll
        for (int i = 0; i < 8; i++) q += xv[i]*xv[i];
        float n2 = warpSum(q);
        float n = sqrtf(fmaxf(n2, EPSF));
        float f = atanhf(fminf(n, CLIP1)) / n * scale;
        float4 o0 = make_float4(f*xv[0], f*xv[1], f*xv[2], f*xv[3]);
        float4 o1 = make_float4(f*xv[4], f*xv[5], f*xv[6], f*xv[7]);
        float* dst = g_v + (size_t)p*256 + lane*8;
        *(float4*)dst = o0;
        *(float4*)(dst + 4) = o1;
        if (lane == 0) g_q2[p] = f*f*n2;
    }
}

// ---------------- per-pixel s ----------------
__device__ __forceinline__ float s_from_q2(int p) {
    int h = (p >> 5) & 31, w = p & 31;
    float np2 = 0.f;
#pragma unroll
    for (int dy = -1; dy <= 1; dy++)
#pragma unroll
        for (int dx = -1; dx <= 1; dx++) {
            int sh = h + dy, sw = w + dx;
            if ((unsigned)sh < 32u && (unsigned)sw < 32u) np2 += g_q2[p + dy*32 + dx];
        }
    float np = sqrtf(fmaxf(np2, EPSF));
    float th = tanhf(np);
    float uf = th / np;
    float un = th;
    if (un > MAXN) { uf *= MAXN/un; un = MAXN; }
    float lam = 2.0f / fmaxf(1.0f - un*un, EPSF);
    return lam * uf;
}

// ---------------- output transform + FC + BN partials; writes NORMALIZED h ----------------
__global__ void wino_out(int znoff) {
    __shared__ float ss[16];
    __shared__ float slam[16];
    __shared__ float sld[16];
    __shared__ float sinv[16];
    __shared__ float ybuf[16][260];
    int t = blockIdx.x, co = threadIdx.x;
    int b = t >> 6, tr = (t >> 3) & 7, tc = t & 7;
    int prow = (b << 10) + (4*tr)*32 + 4*tc;
    if (co < 16) {
        int r = co >> 2, c = co & 3;
        ss[co] = s_from_q2(prow + r*32 + c);
    }
    float m[36];
#pragma unroll
    for (int pos = 0; pos < 36; pos++)
        m[pos] = g_m[((size_t)pos*NTIL + t)*256 + co];
    float Z[4][6];
#pragma unroll
    for (int bb = 0; bb < 6; bb++) {
        float in[6] = { m[bb], m[6+bb], m[12+bb], m[18+bb], m[24+bb], m[30+bb] };
        float out[4];
        at6(in, out);
#pragma unroll
        for (int r = 0; r < 4; r++) Z[r][bb] = out[r];
    }
    float zn = g_zn[znoff + co];
    __syncthreads();
#pragma unroll
    for (int r = 0; r < 4; r++) {
        float Y[4];
        at6(Z[r], Y);
#pragma unroll
        for (int c = 0; c < 4; c++) {
            float s = ss[r*4 + c];
            float tt = Y[c] * s / zn;
            ybuf[r*4 + c][co] = sinhf(2.0f * zn * asinhf(tt));
        }
    }
    __syncthreads();
    int wd = co >> 5, lid = co & 31;
#pragma unroll
    for (int k = 0; k < 2; k++) {
        int pl = wd*2 + k;
        float q = 0.f;
#pragma unroll
        for (int i = 0; i < 8; i++) {
            float v = ybuf[pl][lid*8 + i];
            q += v*v;
        }
        float tot = warpSum(q);
        float inv = 1.0f / (1.0f + sqrtf(1.0f + tot));
        float n2 = tot*inv*inv;
        float lam = 2.0f / fmaxf(1.0f - n2, EPSF);
        if (lid == 0) { slam[pl] = lam*inv; sld[pl] = lam - 1.0f; sinv[pl] = inv; }
    }
    __syncthreads();
    float accm = 0.f;
#pragma unroll
    for (int pl = 0; pl < 16; pl++)
        accm += slam[pl] * ybuf[pl][co];
    g_pm[t*256 + co] = accm;
    if (co == 0) {
        float d = 0.f;
#pragma unroll
        for (int pl = 0; pl < 16; pl++) d += sld[pl];
        g_pd[t] = d;
    }
#pragma unroll
    for (int pl = 0; pl < 16; pl++) {
        int p = prow + (pl >> 2)*32 + (pl & 3);
        g_h[(size_t)p*256 + co] = ybuf[pl][co] * sinv[pl];
    }
}

// ---------------- BN mu: 8-block partial sum + last-block finalize ----------------
__global__ void bnmu_kernel(const float* __restrict__ bias) {
    __shared__ float sb[24];
    __shared__ int slast;
    int c = threadIdx.x;
    float s = 0.f;
    int g0 = blockIdx.x * 128;
    for (int g = 0; g < 128; g++) s += g_pm[(g0 + g)*256 + c];
    g_pm2[blockIdx.x*256 + c] = s;
    __threadfence();
    if (c == 0) slast = (atomicAdd(&g_ctr2, 1) == 7);
    __syncthreads();
    if (!slast) return;
    __threadfence();
    float msum = 0.f;
#pragma unroll
    for (int j = 0; j < 8; j++) msum += g_pm2[j*256 + c];
    float dv = 0.f;
#pragma unroll
    for (int j = 0; j < 4; j++) dv += g_pd[j*256 + c];
    float r1[1] = { dv };
    blockReduceK<1>(r1, sb);
    float den = fmaxf(r1[0], EPSF);
    float m = msum / den;
    float r2[1] = { m*m };
    blockReduceK<1>(r2, sb);
    float nm = sqrtf(fmaxf(r2[0], EPSF));
    float fac = tanhf(0.5f * atanhf(fminf(nm, CLIP1))) / nm;
    float muc = fac * m;
    g_mu[c] = muc;
    float bc = bias[c];
    float r3[3] = { muc*muc, bc*bc, bc*muc };
    blockReduceK<3>(r3, sb);
    if (c == 0) {
        float mu2 = r3[0], b2 = r3[1], bm = r3[2];
        g_sc[0] = mu2;
        g_sc[1] = 2.0f / fmaxf(1.0f - mu2, EPSF);
        g_sc[2] = b2;
        g_sc[3] = 2.0f / fmaxf(1.0f - b2, EPSF);
        g_sc[4] = bm;
        ((volatile float*)g_sc)[5] = 0.f;
        g_ctr2 = 0;
    }
}

// ---------------- variance partial (normalized input) ----------------
__device__ __forceinline__ float var_pixel(int p, const float* mu8, float mu2) {
    int lid = threadIdx.x & 31;
    const float4* row = (const float4*)(g_h + (size_t)p*256 + lid*8);
    float4 a = row[0], cc = row[1];
    float v[8] = {a.x,a.y,a.z,a.w,cc.x,cc.y,cc.z,cc.w};
    float q1 = 0.f, q2 = 0.f;
#pragma unroll
    for (int j = 0; j < 8; j++) { q1 += v[j]*v[j]; q2 += v[j]*mu8[j]; }
    float xp2 = warpSum(q1);
    float ip  = warpSum(q2);
    float A = 1.0f - 2.0f*ip + mu2;
    float B = 1.0f - xp2;
    float nn = fmaxf(A*A*xp2 - 2.0f*A*B*ip + B*B*mu2, 0.f);
    float den = fmaxf(1.0f - 2.0f*ip + xp2*mu2, EPSF);
    float nr = sqrtf(fmaxf(nn/(den*den), EPSF));
    float dd = 2.0f * atanhf(fminf(nr, CLIP1));
    return dd*dd;
}

// ---------------- shared BN point transform ----------------
__device__ __forceinline__ float bn_point_w(const float* xv, const float* mu8, const float* b8,
                                            float* hc) {
    float mu2 = g_sc[0], lam_mu = g_sc[1], b2 = g_sc[2], lam_b = g_sc[3],
          bm = g_sc[4], rstd = g_sc[5];
    float s0 = 0.f, s1 = 0.f, s2 = 0.f;
#pragma unroll
    for (int i = 0; i < 8; i++) { s0 += xv[i]*xv[i]; s1 += mu8[i]*xv[i]; s2 += b8[i]*xv[i]; }
    float xp2 = warpSum(s0), ip = warpSum(s1), bx = warpSum(s2);
    float A  = 1.0f - 2.0f*ip + xp2;
    float Bc = 1.0f - mu2;
    float den = fmaxf(1.0f - 2.0f*ip + mu2*xp2, EPSF);
    float nd2 = fmaxf(A*A*mu2 - 2.0f*A*Bc*ip + Bc*Bc*xp2, 0.f) / (den*den);
    float nd = sqrtf(fmaxf(nd2, EPSF));
    float cv = (2.0f/lam_mu) * atanhf(fminf(nd, CLIP1)) / nd;
    float uw = cv * (Bc*bx - A*bm) / den;
    float vw = cv * (A*mu2 - Bc*ip) / den;
    float av  = -uw*mu2 - vw - 2.0f*bm*vw;
    float bv2 = -vw*b2 + uw;
    float dgy = fmaxf(1.0f - 2.0f*bm + b2*mu2, EPSF);
    float fac = (lam_mu / lam_b) * rstd;
    float uc[8];
    float t0 = 0.f, t1 = 0.f;
#pragma unroll
    for (int i = 0; i < 8; i++) {
        float vc = cv * (Bc*xv[i] - A*mu8[i]) / den;
        uc[i] = (vc + 2.0f*(av*b8[i] - bv2*mu8[i]) / dgy) * fac;
        t0 += uc[i]*uc[i];
        t1 += b8[i]*uc[i];
    }
    float u2 = warpSum(t0), bu = warpSum(t1);
    float nu = sqrtf(fmaxf(u2, EPSF));
    float tf = tanhf(0.5f * lam_b * nu) / nu;
    float s2m = tf*tf*u2;
    float bs  = tf*bu;
    float A3 = 1.0f + 2.0f*bs + s2m, B3 = 1.0f - b2;
    float den3 = fmaxf(1.0f + 2.0f*bs + b2*s2m, EPSF);
#pragma unroll
    for (int i = 0; i < 8; i++) hc[i] = (A3*b8[i] + B3*tf*uc[i]) / den3;
    float nh2 = fmaxf(A3*A3*b2 + 2.0f*A3*B3*bs + B3*B3*s2m, 0.f) / (den3*den3);
    float nh = sqrtf(fmaxf(nh2, EPSF));
    if (nh > MAXN) {
        float q = MAXN / nh;
#pragma unroll
        for (int i = 0; i < 8; i++) hc[i] *= q;
        nh = MAXN;
    }
    return nh;
}

// ---------------- FUSED variance + BN apply + hrelu + pre-for-conv2 ----------------
__global__ void bnva_kernel(const float* __restrict__ bias, const float* __restrict__ weight,
                            float scale) {
    __shared__ float sv[8];
    __shared__ int slast;
    int wid = threadIdx.x >> 5, lid = threadIdx.x & 31;
    int p0 = blockIdx.x * 64;
    float mu8[8];
#pragma unroll
    for (int j = 0; j < 8; j++) mu8[j] = g_mu[lid*8 + j];
    float mu2 = g_sc[0];
    float acc = 0.f;
    for (int i = 0; i < 8; i++)
        acc += var_pixel(p0 + wid*8 + i, mu8, mu2);
    if (lid == 0) sv[wid] = acc;
    __syncthreads();
    if (threadIdx.x == 0) {
        float s = 0.f;
        for (int w = 0; w < 8; w++) s += sv[w];
        g_pv[blockIdx.x] = s;
        __threadfence();
        slast = (atomicAdd(&g_ctr, 1) == 255);
    }
    __syncthreads();
    if (slast) {
        float v = g_pv[threadIdx.x];
        __shared__ float sb[8];
        float r[1] = { v };
        blockReduceK<1>(r, sb);
        if (threadIdx.x == 0) {
            float var = r[0] / 16384.0f;
            g_ctr = 0;
            __threadfence();
            ((volatile float*)g_sc)[5] = sqrtf(weight[0] / fmaxf(var, EPSF));
        }
    }
    if (threadIdx.x == 0) {
        volatile float* vs = g_sc;
        while (vs[5] == 0.f) { }
    }
    __syncthreads();
    float b8[8];
#pragma unroll
    for (int j = 0; j < 8; j++) b8[j] = bias[lid*8 + j];
    for (int i = 0; i < 8; i++) {
        int p = p0 + wid*8 + i;
        const float4* row = (const float4*)(g_h + (size_t)p*256 + lid*8);
        float4 a = row[0], cc = row[1];
        float xv[8] = {a.x,a.y,a.z,a.w,cc.x,cc.y,cc.z,cc.w};
        float hc[8];
        float nh = bn_point_w(xv, mu8, b8, hc);
        float lf = atanhf(fminf(nh, CLIP1)) / nh;
        float rc[8];
        float q = 0.f;
#pragma unroll
        for (int k = 0; k < 8; k++) { rc[k] = fmaxf(lf*hc[k], 0.f); q += rc[k]*rc[k]; }
        float rs = warpSum(q);
        float nr = sqrtf(fmaxf(rs, EPSF));
        float ef = tanhf(nr) / nr;
        float nhr = sqrtf(fmaxf(ef*ef*rs, EPSF));
        float adj = 1.0f;
        if (nhr > MAXN) { adj = MAXN/nhr; nhr = MAXN; }
        float f3 = atanhf(fminf(nhr, CLIP1)) / nhr * scale;
        float g = f3 * ef * adj;
        float4 o0 = make_float4(g*rc[0], g*rc[1], g*rc[2], g*rc[3]);
        float4 o1 = make_float4(g*rc[4], g*rc[5], g*rc[6], g*rc[7]);
        float* dst = g_v + (size_t)p*256 + lid*8;
        *(float4*)dst = o0;
        *(float4*)(dst + 4) = o1;
        if (lid == 0) g_q2[p] = f3*f3*nhr*nhr;
    }
}

// ---------------- FUSED variance + BN2 apply + residual + hrelu + NCHW out ----------------
__global__ void bnvf_kernel(const float* __restrict__ bias, const float* __restrict__ weight,
                            float* __restrict__ out) {
    __shared__ float so[256][33];
    __shared__ float sv[8];
    __shared__ int slast;
    int tid = threadIdx.x, lane = tid & 31, w8 = tid >> 5;
    int p0 = blockIdx.x * 32;
    int b = p0 >> 10, hw0 = p0 & 1023;
    float mu8[8], b8[8];
#pragma unroll
    for (int j = 0; j < 8; j++) { mu8[j] = g_mu[lane*8 + j]; b8[j] = bias[lane*8 + j]; }
    float mu2 = g_sc[0];
    float acc = 0.f;
    for (int i = 0; i < 4; i++)
        acc += var_pixel(p0 + w8*4 + i, mu8, mu2);
    if (lane == 0) sv[w8] = acc;
    __syncthreads();
    if (tid == 0) {
        float s = 0.f;
        for (int w = 0; w < 8; w++) s += sv[w];
        g_pv[blockIdx.x] = s;
        __threadfence();
        slast = (atomicAdd(&g_ctr, 1) == 511);
    }
    __syncthreads();
    if (slast) {
        float v = g_pv[tid] + g_pv[tid + 256];
        __shared__ float sb[8];
        float r[1] = { v };
        blockReduceK<1>(r, sb);
        if (tid == 0) {
            float var = r[0] / 16384.0f;
            g_ctr = 0;
            __threadfence();
            ((volatile float*)g_sc)[5] = sqrtf(weight[0] / fmaxf(var, EPSF));
        }
    }
    if (tid == 0) {
        volatile float* vs = g_sc;
        while (vs[5] == 0.f) { }
    }
    __syncthreads();
#pragma unroll
    for (int pp = 0; pp < 4; pp++) {
        int pl = w8*4 + pp;
        int p = p0 + pl;
        const float4* row = (const float4*)(g_h + (size_t)p*256 + lane*8);
        float4 a = row[0], cc = row[1];
        float xv[8] = {a.x,a.y,a.z,a.w,cc.x,cc.y,cc.z,cc.w};
        float hc[8];
        float nh = bn_point_w(xv, mu8, b8, hc);
        const float4* rrow = (const float4*)(g_xl + (size_t)p*256 + lane*8);
        float4 r0 = rrow[0], r1 = rrow[1];
        float res[8] = {r0.x,r0.y,r0.z,r0.w,r1.x,r1.y,r1.z,r1.w};
        float q1 = 0.f, q2 = 0.f;
#pragma unroll
        for (int i = 0; i < 8; i++) { q1 += res[i]*res[i]; q2 += hc[i]*res[i]; }
        float y2 = warpSum(q1), xy = warpSum(q2);
        float x2 = nh*nh;
        float A4 = 1.0f + 2.0f*xy + y2, B4 = 1.0f - x2;
        float den4 = fmaxf(1.0f + 2.0f*xy + x2*y2, EPSF);
        float hm[8];
#pragma unroll
        for (int i = 0; i < 8; i++) hm[i] = (A4*hc[i] + B4*res[i]) / den4;
        float nm2 = fmaxf(A4*A4*x2 + 2.0f*A4*B4*xy + B4*B4*y2, 0.f) / (den4*den4);
        float nmv = sqrtf(fmaxf(nm2, EPSF));
        float lf = atanhf(fminf(nmv, CLIP1)) / nmv;
        float rc[8];
        float q = 0.f;
#pragma unroll
        for (int i = 0; i < 8; i++) { rc[i] = fmaxf(lf*hm[i], 0.f); q += rc[i]*rc[i]; }
        float rs = warpSum(q);
        float nr = sqrtf(fmaxf(rs, EPSF));
        float ef = tanhf(nr) / nr;
        float nhr = sqrtf(fmaxf(ef*ef*rs, EPSF));
        float adj = (nhr > MAXN) ? MAXN/nhr : 1.0f;
#pragma unroll
        for (int i = 0; i < 8; i++) so[lane*8 + i][pl] = ef * adj * rc[i];
    }
    __syncthreads();
#pragma unroll 8
    for (int i = 0; i < 32; i++) {
        int c = i*8 + w8;
        out[(size_t)(b*256 + c)*1024 + hw0 + lane] = so[c][lane];
    }
}

// ---------------- launcher ----------------
extern "C" void kernel_launch(void* const* d_in, const int* in_sizes, int n_in,
                              void* d_out, int out_size) {
    const float* x  = (const float*)d_in[0];
    const float* z1 = (const float*)d_in[1];
    const float* z2 = (const float*)d_in[2];
    const float* w1 = (const float*)d_in[3];
    const float* b1 = (const float*)d_in[4];
    const float* w2 = (const float*)d_in[5];
    const float* b2 = (const float*)d_in[6];
    float* out = (float*)d_out;

    // scale = Beta(1152, 0.5) / Beta(128, 0.5)
    double lg = lgamma(1152.0) - lgamma(1152.5) - lgamma(128.0) + lgamma(128.5);
    float scale = (float)exp(lg);

    static int smem_set = 0;
    if (!smem_set) {
        cudaFuncSetAttribute(wino_gemm, cudaFuncAttributeMaxDynamicSharedMemorySize, CONV_SMEM);
        smem_set = 1;
    }

    dim3 ggrid(8, 4, 12);

    wino_u<<<dim3(256, 2), 256>>>(z1, z2);       // 0
    pre2_kernel<<<PNUM/32, 256>>>(x, scale);     // 1
    wino_in<<<NTIL, 256>>>();                    // 2
    wino_gemm<<<ggrid, 256, CONV_SMEM>>>(0);     // 3  <- ncu capture target
    wino_out<<<NTIL, 256>>>(0);

    bnmu_kernel<<<8, 256>>>(b1);
    bnva_kernel<<<256, 256>>>(b1, w1, scale);

    wino_in<<<NTIL, 256>>>();
    wino_gemm<<<ggrid, 256, CONV_SMEM>>>(1);
    wino_out<<<NTIL, 256>>>(256);

    bnmu_kernel<<<8, 256>>>(b2);
    bnvf_kernel<<<512, 256>>>(b2, w2, out);
}

// round 14
// speedup vs baseline: 1.0573x; 1.0573x over previous
#include <cuda_runtime.h>
#include <cuda_bf16.h>
#include <math.h>
#include <stdint.h>

// Problem constants: B=16, C=256, H=W=32
#define PNUM 16384
#define CNUM 256
#define CLIP1 0.9999999f
#define MAXN  0.99999f
#define EPSF  1e-15f

#define NPOS 36
#define NTIL 1024
#define STAGE_BYTES 24576u       // Ahi 8K + Alo 8K + Bhi 4K + Blo 4K
#define CONV_SMEM (3*24576)      // 72 KB -> 3 CTAs/SM

// ---------------- device scratch ----------------
__device__ __align__(16) float g_v [PNUM*CNUM];
__device__ __align__(16) __nv_bfloat16 g_Vhi[NPOS*NTIL*CNUM];
__device__ __align__(16) __nv_bfloat16 g_Vlo[NPOS*NTIL*CNUM];
__device__ __align__(16) __nv_bfloat16 g_uhi1[NPOS*CNUM*CNUM];
__device__ __align__(16) __nv_bfloat16 g_ulo1[NPOS*CNUM*CNUM];
__device__ __align__(16) __nv_bfloat16 g_uhi2[NPOS*CNUM*CNUM];
__device__ __align__(16) __nv_bfloat16 g_ulo2[NPOS*CNUM*CNUM];
__device__ __align__(16) float g_m [NPOS*NTIL*CNUM];
__device__ __align__(16) float g_h [PNUM*CNUM];   // NORMALIZED h (post FC)
__device__ __align__(16) float g_xl[PNUM*CNUM];
__device__ float g_q2[PNUM];
__device__ float g_zn[512];
__device__ float g_pm [NTIL*CNUM];
__device__ float g_pm2[8*CNUM];
__device__ float g_pd[NTIL];
__device__ float g_pv[512];
__device__ float g_mu[CNUM];
__device__ float g_sc[8];
__device__ int   g_ctr  = 0;
__device__ int   g_ctr2 = 0;

// ---------------- PTX helpers ----------------
__device__ __forceinline__ uint32_t smem_u32(const void* p) {
    uint32_t a;
    asm("{ .reg .u64 t; cvta.to.shared.u64 t, %1; cvt.u32.u64 %0, t; }" : "=r"(a) : "l"(p));
    return a;
}
__device__ __forceinline__ void cpa16(uint32_t dst, const void* src) {
    asm volatile("cp.async.cg.shared.global [%0], [%1], 16;" :: "r"(dst), "l"(src) : "memory");
}
__device__ __forceinline__ void cp_commit() {
    asm volatile("cp.async.commit_group;" ::: "memory");
}
template<int N>
__device__ __forceinline__ void cp_wait() {
    asm volatile("cp.async.wait_group %0;" :: "n"(N) : "memory");
}
__device__ __forceinline__ void ldsm4(uint32_t* r, uint32_t addr) {
    asm volatile("ldmatrix.sync.aligned.m8n8.x4.shared.b16 {%0,%1,%2,%3}, [%4];"
        : "=r"(r[0]), "=r"(r[1]), "=r"(r[2]), "=r"(r[3]) : "r"(addr));
}
__device__ __forceinline__ void mma16816(float* d, const uint32_t* a, const uint32_t* b) {
    asm volatile("mma.sync.aligned.m16n8k16.row.col.f32.bf16.bf16.f32 "
        "{%0,%1,%2,%3}, {%4,%5,%6,%7}, {%8,%9}, {%0,%1,%2,%3};"
        : "+f"(d[0]), "+f"(d[1]), "+f"(d[2]), "+f"(d[3])
        : "r"(a[0]), "r"(a[1]), "r"(a[2]), "r"(a[3]), "r"(b[0]), "r"(b[1]));
}
__device__ __forceinline__ uint32_t swz(int r, int c) {
    return (uint32_t)(((r >> 1) << 7) | (((((r & 1) << 2) | c) ^ ((r >> 1) & 7)) << 4));
}

// ---------------- reductions ----------------
__device__ __forceinline__ float warpSum(float v) {
#pragma unroll
    for (int o = 16; o > 0; o >>= 1) v += __shfl_xor_sync(0xffffffffu, v, o);
    return v;
}
template<int K>
__device__ __forceinline__ void blockReduceK(float* v, float* sbuf) {
    int tid = threadIdx.x, lane = tid & 31, wid = tid >> 5;
#pragma unroll
    for (int i = 0; i < K; i++) {
        float x = v[i];
#pragma unroll
        for (int o = 16; o > 0; o >>= 1) x += __shfl_down_sync(0xffffffffu, x, o);
        if (lane == 0) sbuf[i*8 + wid] = x;
    }
    __syncthreads();
    if (tid == 0) {
#pragma unroll
        for (int i = 0; i < K; i++) {
            float s = sbuf[i*8];
            for (int w = 1; w < 8; w++) s += sbuf[i*8 + w];
            sbuf[i*8] = s;
        }
    }
    __syncthreads();
#pragma unroll
    for (int i = 0; i < K; i++) v[i] = sbuf[i*8];
    __syncthreads();
}

// ---------------- Winograd transforms ----------------
__device__ __forceinline__ void bt6(const float* in, float* out) {
    out[0] =  4.f*in[0] - 5.f*in[2] + in[4];
    out[1] = -4.f*in[1] - 4.f*in[2] + in[3] + in[4];
    out[2] =  4.f*in[1] - 4.f*in[2] - in[3] + in[4];
    out[3] = -2.f*in[1] -     in[2] + 2.f*in[3] + in[4];
    out[4] =  2.f*in[1] -     in[2] - 2.f*in[3] + in[4];
    out[5] =  4.f*in[1] - 5.f*in[3] + in[5];
}
__device__ __forceinline__ void g6(const float* in, float* out) {
    out[0] = 0.25f*in[0];
    out[1] = -(in[0] + in[1] + in[2]) * (1.f/6.f);
    out[2] = (-in[0] + in[1] - in[2]) * (1.f/6.f);
    out[3] = in[0]*(1.f/24.f) + in[1]*(1.f/12.f) + in[2]*(1.f/6.f);
    out[4] = in[0]*(1.f/24.f) - in[1]*(1.f/12.f) + in[2]*(1.f/6.f);
    out[5] = in[2];
}
__device__ __forceinline__ void at6(const float* in, float* out) {
    out[0] = in[0] + in[1] + in[2] + in[3] + in[4];
    out[1] = in[1] - in[2] + 2.f*(in[3] - in[4]);
    out[2] = in[1] + in[2] + 4.f*(in[3] + in[4]);
    out[3] = in[1] - in[2] + 8.f*(in[3] - in[4]) + in[5];
}

// ---------------- U = G z G^T (+ fused z column norms), both weight sets ----------------
__global__ void wino_u(const float* __restrict__ z1, const float* __restrict__ z2) {
    __shared__ float sb[8];
    const float* z = blockIdx.y ? z2 : z1;
    __nv_bfloat16* uh = blockIdx.y ? g_uhi2 : g_uhi1;
    __nv_bfloat16* ul = blockIdx.y ? g_ulo2 : g_ulo1;
    int co = blockIdx.x, ci = threadIdx.x;
    float g[3][3];
    float nsum = 0.f;
#pragma unroll
    for (int i = 0; i < 3; i++)
#pragma unroll
        for (int j = 0; j < 3; j++) {
            float w = z[(size_t)((i*3 + j)*256 + ci)*256 + co];
            g[i][j] = w;
            nsum += w*w;
        }
    float r1[1] = { nsum };
    blockReduceK<1>(r1, sb);
    if (ci == 0) g_zn[blockIdx.y*256 + co] = sqrtf(fmaxf(r1[0], EPSF));

    float t[6][3];
#pragma unroll
    for (int j = 0; j < 3; j++) {
        float in[3] = { g[0][j], g[1][j], g[2][j] };
        float out[6];
        g6(in, out);
#pragma unroll
        for (int a = 0; a < 6; a++) t[a][j] = out[a];
    }
#pragma unroll
    for (int a = 0; a < 6; a++) {
        float out[6];
        g6(t[a], out);
#pragma unroll
        for (int b = 0; b < 6; b++) {
            float u = out[b];
            __nv_bfloat16 hi = __float2bfloat16(u);
            size_t idx = ((size_t)((a*6 + b)*256 + co))*256 + ci;
            uh[idx] = hi;
            ul[idx] = __float2bfloat16(u - __bfloat162float(hi));
        }
    }
}

// ---------------- V = B^T d B per tile ----------------
__global__ void wino_in() {
    int t = blockIdx.x, ci = threadIdx.x;
    int b = t >> 6, tr = (t >> 3) & 7, tc = t & 7;
    int base = b << 10;
    float d[6][6];
#pragma unroll
    for (int y = 0; y < 6; y++) {
        int iy = 4*tr - 1 + y;
#pragma unroll
        for (int x = 0; x < 6; x++) {
            int ix = 4*tc - 1 + x;
            bool ok = ((unsigned)iy < 32u) && ((unsigned)ix < 32u);
            d[y][x] = ok ? g_v[(size_t)(base + iy*32 + ix)*256 + ci] : 0.f;
        }
    }
    float e[6][6];
#pragma unroll
    for (int x = 0; x < 6; x++) {
        float in[6] = { d[0][x], d[1][x], d[2][x], d[3][x], d[4][x], d[5][x] };
        float out[6];
        bt6(in, out);
#pragma unroll
        for (int a = 0; a < 6; a++) e[a][x] = out[a];
    }
#pragma unroll
    for (int a = 0; a < 6; a++) {
        float out[6];
        bt6(e[a], out);
#pragma unroll
        for (int bb = 0; bb < 6; bb++) {
            float v = out[bb];
            __nv_bfloat16 hi = __float2bfloat16(v);
            size_t idx = ((size_t)((a*6 + bb)*NTIL + t))*256 + ci;
            g_Vhi[idx] = hi;
            g_Vlo[idx] = __float2bfloat16(v - __bfloat162float(hi));
        }
    }
}

// ---------------- batched Winograd GEMM (R11/R12 proven shape, reverted) ----------------
__global__ void __launch_bounds__(256, 3) wino_gemm(int which) {
    extern __shared__ __align__(16) char dsm[];
    uint32_t sbase = smem_u32(dsm);

    const __nv_bfloat16* Bh = which ? g_uhi2 : g_uhi1;
    const __nv_bfloat16* Bl = which ? g_ulo2 : g_ulo1;
    int t0  = blockIdx.x << 7;
    int nq  = blockIdx.y;
    int pos = blockIdx.z;

    int tid = threadIdx.x, wid = tid >> 5, l = tid & 31;

    int c4 = tid & 3;
    int r0 = tid >> 2;
    uint32_t ph0 = swz(r0, c4), ph1 = swz(r0 + 64, c4);
    const __nv_bfloat16* Abase_hi = g_Vhi + ((size_t)pos*NTIL + t0)*256;
    const __nv_bfloat16* Abase_lo = g_Vlo + ((size_t)pos*NTIL + t0)*256;
    const __nv_bfloat16* Bbase_hi = Bh + ((size_t)pos*256 + nq*64)*256;
    const __nv_bfloat16* Bbase_lo = Bl + ((size_t)pos*256 + nq*64)*256;
    size_t a0 = (size_t)r0*256 + c4*8, a1 = (size_t)(r0 + 64)*256 + c4*8;

    int m0 = (wid & 3) << 5;
    int n0w = (wid >> 2) << 5;
    int mi = l >> 3;
    int rA = m0 + ((mi & 1) << 3) + (l & 7);
    uint32_t qA0 = swz(rA, mi >> 1);
    int rB = n0w + (((mi >> 1) & 1) << 3) + (l & 7);
    uint32_t qB0 = swz(rB, mi & 1);

    float acc[2][4][4];
#pragma unroll
    for (int i = 0; i < 2; i++)
#pragma unroll
        for (int j = 0; j < 4; j++)
#pragma unroll
            for (int k = 0; k < 4; k++) acc[i][j][k] = 0.f;

    auto load_chunk = [&](int kc, int stage) {
        size_t coff = (size_t)(kc << 5);
        uint32_t st = sbase + (uint32_t)stage*STAGE_BYTES;
        cpa16(st + ph0,         Abase_hi + a0 + coff);
        cpa16(st + 8192 + ph0,  Abase_lo + a0 + coff);
        cpa16(st + ph1,         Abase_hi + a1 + coff);
        cpa16(st + 8192 + ph1,  Abase_lo + a1 + coff);
        cpa16(st + 16384 + ph0, Bbase_hi + a0 + coff);
        cpa16(st + 20480 + ph0, Bbase_lo + a0 + coff);
        cp_commit();
    };

    load_chunk(0, 0);
    load_chunk(1, 1);

    for (int kc = 0; kc < 8; kc++) {
        int stage = kc % 3;
        if (kc < 6) cp_wait<1>(); else cp_wait<0>();
        __syncthreads();
        if (kc + 2 < 8) load_chunk(kc + 2, (kc + 2) % 3);

        uint32_t st = sbase + (uint32_t)stage*STAGE_BYTES;
        uint32_t Ahi = st, Alo = st + 8192, Bhi = st + 16384, Blo = st + 20480;
#pragma unroll
        for (int ks = 0; ks < 2; ks++) {
            uint32_t kx = (uint32_t)(ks << 5);
            uint32_t qa = qA0 ^ kx, qb = qB0 ^ kx;
            uint32_t ah[8], al[8], bbv[8];
            ldsm4(bbv,     Bhi + qb);
            ldsm4(bbv + 4, Bhi + qb + 1024);
            ldsm4(ah,     Ahi + qa);
            ldsm4(ah + 4, Ahi + qa + 1024);
            ldsm4(al,     Alo + qa);
            ldsm4(al + 4, Alo + qa + 1024);
#pragma unroll
            for (int nf = 0; nf < 4; nf++) {
                const uint32_t* bp = bbv + nf*2;
                mma16816(acc[0][nf], ah,     bp);
                mma16816(acc[1][nf], ah + 4, bp);
            }
#pragma unroll
            for (int nf = 0; nf < 4; nf++) {
                const uint32_t* bp = bbv + nf*2;
                mma16816(acc[0][nf], al,     bp);
                mma16816(acc[1][nf], al + 4, bp);
            }
            ldsm4(bbv,     Blo + qb);
            ldsm4(bbv + 4, Blo + qb + 1024);
#pragma unroll
            for (int nf = 0; nf < 4; nf++) {
                const uint32_t* bp = bbv + nf*2;
                mma16816(acc[0][nf], ah,     bp);
                mma16816(acc[1][nf], ah + 4, bp);
            }
        }
    }

    int row0 = m0 + (l >> 2);
    int col0 = n0w + ((l & 3) << 1);
    float* gm = g_m + ((size_t)pos*NTIL + t0)*256 + nq*64;
#pragma unroll
    for (int mf = 0; mf < 2; mf++)
#pragma unroll
        for (int hf = 0; hf < 2; hf++) {
            int r = row0 + mf*16 + hf*8;
            float* rowp = gm + (size_t)r*256;
#pragma unroll
            for (int nf = 0; nf < 4; nf++)
                *(float2*)(rowp + col0 + nf*8) =
                    make_float2(acc[mf][nf][hf*2], acc[mf][nf][hf*2 + 1]);
        }
}

// ---------------- pre2 (+ fused xT) ----------------
__global__ void pre2_kernel(const float* __restrict__ x, float scale) {
    __shared__ float sx[256][33];
    int tid = threadIdx.x, lane = tid & 31, w8 = tid >> 5;
    int p0 = blockIdx.x * 32;
    int b = p0 >> 10, hw0 = p0 & 1023;
#pragma unroll 8
    for (int i = 0; i < 32; i++) {
        int c = i*8 + w8;
        sx[c][lane] = x[(size_t)(b*256 + c)*1024 + hw0 + lane];
    }
    __syncthreads();
#pragma unroll 8
    for (int pl = 0; pl < 32; pl++)
        g_xl[(size_t)(p0 + pl)*256 + tid] = sx[tid][pl];
#pragma unroll
    for (int pp = 0; pp < 4; pp++) {
        int pl = w8*4 + pp;
        int p = p0 + pl;
        float xv[8];
#pragma unroll
        for (int i = 0; i < 8; i++) xv[i] = sx[lane*8 + i][pl];
        float q = 0.f;
#pragma unroll
        for (int i = 0; i < 8; i++) q += xv[i]*xv[i];
        float n2 = warpSum(q);
        float n = sqrtf(fmaxf(n2, EPSF));
        float f = atanhf(fminf(n, CLIP1)) / n * scale;
        float4 o0 = make_float4(f*xv[0], f*xv[1], f*xv[2], f*xv[3]);
        float4 o1 = make_float4(f*xv[4], f*xv[5], f*xv[6], f*xv[7]);
        float* dst = g_v + (size_t)p*256 + lane*8;
        *(float4*)dst = o0;
        *(float4*)(dst + 4) = o1;
        if (lane == 0) g_q2[p] = f*f*n2;
    }
}

// ---------------- per-pixel s ----------------
__device__ __forceinline__ float s_from_q2(int p) {
    int h = (p >> 5) & 31, w = p & 31;
    float np2 = 0.f;
#pragma unroll
    for (int dy = -1; dy <= 1; dy++)
#pragma unroll
        for (int dx = -1; dx <= 1; dx++) {
            int sh = h + dy, sw = w + dx;
            if ((unsigned)sh < 32u && (unsigned)sw < 32u) np2 += g_q2[p + dy*32 + dx];
        }
    float np = sqrtf(fmaxf(np2, EPSF));
    float th = tanhf(np);
    float uf = th / np;
    float un = th;
    if (un > MAXN) { uf *= MAXN/un; un = MAXN; }
    float lam = 2.0f / fmaxf(1.0f - un*un, EPSF);
    return lam * uf;
}

// ---------------- output transform + FC + BN partials; writes NORMALIZED h ----------------
// fast path: sinh(a*asinh(t)) = 0.5*(w^a - w^-a), w = t + sqrt(t^2+1)
__global__ void wino_out(int znoff) {
    __shared__ float ss[16];
    __shared__ float slam[16];
    __shared__ float sld[16];
    __shared__ float sinv[16];
    __shared__ float ybuf[16][260];
    int t = blockIdx.x, co = threadIdx.x;
    int b = t >> 6, tr = (t >> 3) & 7, tc = t & 7;
    int prow = (b << 10) + (4*tr)*32 + 4*tc;
    if (co < 16) {
        int r = co >> 2, c = co & 3;
        ss[co] = s_from_q2(prow + r*32 + c);
    }
    float m[36];
#pragma unroll
    for (int pos = 0; pos < 36; pos++)
        m[pos] = g_m[((size_t)pos*NTIL + t)*256 + co];
    float Z[4][6];
#pragma unroll
    for (int bb = 0; bb < 6; bb++) {
        float in[6] = { m[bb], m[6+bb], m[12+bb], m[18+bb], m[24+bb], m[30+bb] };
        float out[4];
        at6(in, out);
#pragma unroll
        for (int r = 0; r < 4; r++) Z[r][bb] = out[r];
    }
    float zn = g_zn[znoff + co];
    float izn = 1.0f / zn;
    float a2 = 2.0f * zn;
    __syncthreads();
#pragma unroll
    for (int r = 0; r < 4; r++) {
        float Y[4];
        at6(Z[r], Y);
#pragma unroll
        for (int c = 0; c < 4; c++) {
            float s = ss[r*4 + c];
            float tt = Y[c] * s * izn;
            float w = tt + sqrtf(fmaf(tt, tt, 1.0f));
            float u = __logf(w);
            float e = __expf(a2 * u);
            ybuf[r*4 + c][co] = 0.5f * (e - 1.0f/e);
        }
    }
    __syncthreads();
    int wd = co >> 5, lid = co & 31;
#pragma unroll
    for (int k = 0; k < 2; k++) {
        int pl = wd*2 + k;
        float q = 0.f;
#pragma unroll
        for (int i = 0; i < 8; i++) {
            float v = ybuf[pl][lid*8 + i];
            q += v*v;
        }
        float tot = warpSum(q);
        float inv = 1.0f / (1.0f + sqrtf(1.0f + tot));
        float n2 = tot*inv*inv;
        float lam = 2.0f / fmaxf(1.0f - n2, EPSF);
        if (lid == 0) { slam[pl] = lam*inv; sld[pl] = lam - 1.0f; sinv[pl] = inv; }
    }
    __syncthreads();
    float accm = 0.f;
#pragma unroll
    for (int pl = 0; pl < 16; pl++)
        accm += slam[pl] * ybuf[pl][co];
    g_pm[t*256 + co] = accm;
    if (co == 0) {
        float d = 0.f;
#pragma unroll
        for (int pl = 0; pl < 16; pl++) d += sld[pl];
        g_pd[t] = d;
    }
#pragma unroll
    for (int pl = 0; pl < 16; pl++) {
        int p = prow + (pl >> 2)*32 + (pl & 3);
        g_h[(size_t)p*256 + co] = ybuf[pl][co] * sinv[pl];
    }
}

// ---------------- BN mu: 8-block partial sum + last-block finalize ----------------
__global__ void bnmu_kernel(const float* __restrict__ bias) {
    __shared__ float sb[24];
    __shared__ int slast;
    int c = threadIdx.x;
    float s = 0.f;
    int g0 = blockIdx.x * 128;
    for (int g = 0; g < 128; g++) s += g_pm[(g0 + g)*256 + c];
    g_pm2[blockIdx.x*256 + c] = s;
    __threadfence();
    if (c == 0) slast = (atomicAdd(&g_ctr2, 1) == 7);
    __syncthreads();
    if (!slast) return;
    __threadfence();
    float msum = 0.f;
#pragma unroll
    for (int j = 0; j < 8; j++) msum += g_pm2[j*256 + c];
    float dv = 0.f;
#pragma unroll
    for (int j = 0; j < 4; j++) dv += g_pd[j*256 + c];
    float r1[1] = { dv };
    blockReduceK<1>(r1, sb);
    float den = fmaxf(r1[0], EPSF);
    float m = msum / den;
    float r2[1] = { m*m };
    blockReduceK<1>(r2, sb);
    float nm = sqrtf(fmaxf(r2[0], EPSF));
    float fac = tanhf(0.5f * atanhf(fminf(nm, CLIP1))) / nm;
    float muc = fac * m;
    g_mu[c] = muc;
    float bc = bias[c];
    float r3[3] = { muc*muc, bc*bc, bc*muc };
    blockReduceK<3>(r3, sb);
    if (c == 0) {
        float mu2 = r3[0], b2 = r3[1], bm = r3[2];
        g_sc[0] = mu2;
        g_sc[1] = 2.0f / fmaxf(1.0f - mu2, EPSF);
        g_sc[2] = b2;
        g_sc[3] = 2.0f / fmaxf(1.0f - b2, EPSF);
        g_sc[4] = bm;
        ((volatile float*)g_sc)[5] = 0.f;
        g_ctr2 = 0;
    }
}

// ---------------- variance partial (normalized input) ----------------
__device__ __forceinline__ float var_pixel(int p, const float* mu8, float mu2) {
    int lid = threadIdx.x & 31;
    const float4* row = (const float4*)(g_h + (size_t)p*256 + lid*8);
    float4 a = row[0], cc = row[1];
    float v[8] = {a.x,a.y,a.z,a.w,cc.x,cc.y,cc.z,cc.w};
    float q1 = 0.f, q2 = 0.f;
#pragma unroll
    for (int j = 0; j < 8; j++) { q1 += v[j]*v[j]; q2 += v[j]*mu8[j]; }
    float xp2 = warpSum(q1);
    float ip  = warpSum(q2);
    float A = 1.0f - 2.0f*ip + mu2;
    float B = 1.0f - xp2;
    float nn = fmaxf(A*A*xp2 - 2.0f*A*B*ip + B*B*mu2, 0.f);
    float den = fmaxf(1.0f - 2.0f*ip + xp2*mu2, EPSF);
    float nr = sqrtf(fmaxf(nn/(den*den), EPSF));
    float dd = 2.0f * atanhf(fminf(nr, CLIP1));
    return dd*dd;
}

// ---------------- shared BN point transform ----------------
__device__ __forceinline__ float bn_point_w(const float* xv, const float* mu8, const float* b8,
                                            float* hc) {
    float mu2 = g_sc[0], lam_mu = g_sc[1], b2 = g_sc[2], lam_b = g_sc[3],
          bm = g_sc[4], rstd = g_sc[5];
    float s0 = 0.f, s1 = 0.f, s2 = 0.f;
#pragma unroll
    for (int i = 0; i < 8; i++) { s0 += xv[i]*xv[i]; s1 += mu8[i]*xv[i]; s2 += b8[i]*xv[i]; }
    float xp2 = warpSum(s0), ip = warpSum(s1), bx = warpSum(s2);
    float A  = 1.0f - 2.0f*ip + xp2;
    float Bc = 1.0f - mu2;
    float den = fmaxf(1.0f - 2.0f*ip + mu2*xp2, EPSF);
    float nd2 = fmaxf(A*A*mu2 - 2.0f*A*Bc*ip + Bc*Bc*xp2, 0.f) / (den*den);
    float nd = sqrtf(fmaxf(nd2, EPSF));
    float cv = (2.0f/lam_mu) * atanhf(fminf(nd, CLIP1)) / nd;
    float uw = cv * (Bc*bx - A*bm) / den;
    float vw = cv * (A*mu2 - Bc*ip) / den;
    float av  = -uw*mu2 - vw - 2.0f*bm*vw;
    float bv2 = -vw*b2 + uw;
    float dgy = fmaxf(1.0f - 2.0f*bm + b2*mu2, EPSF);
    float fac = (lam_mu / lam_b) * rstd;
    float uc[8];
    float t0 = 0.f, t1 = 0.f;
#pragma unroll
    for (int i = 0; i < 8; i++) {
        float vc = cv * (Bc*xv[i] - A*mu8[i]) / den;
        uc[i] = (vc + 2.0f*(av*b8[i] - bv2*mu8[i]) / dgy) * fac;
        t0 += uc[i]*uc[i];
        t1 += b8[i]*uc[i];
    }
    float u2 = warpSum(t0), bu = warpSum(t1);
    float nu = sqrtf(fmaxf(u2, EPSF));
    float tf = tanhf(0.5f * lam_b * nu) / nu;
    float s2m = tf*tf*u2;
    float bs  = tf*bu;
    float A3 = 1.0f + 2.0f*bs + s2m, B3 = 1.0f - b2;
    float den3 = fmaxf(1.0f + 2.0f*bs + b2*s2m, EPSF);
#pragma unroll
    for (int i = 0; i < 8; i++) hc[i] = (A3*b8[i] + B3*tf*uc[i]) / den3;
    float nh2 = fmaxf(A3*A3*b2 + 2.0f*A3*B3*bs + B3*B3*s2m, 0.f) / (den3*den3);
    float nh = sqrtf(fmaxf(nh2, EPSF));
    if (nh > MAXN) {
        float q = MAXN / nh;
#pragma unroll
        for (int i = 0; i < 8; i++) hc[i] *= q;
        nh = MAXN;
    }
    return nh;
}

// ---------------- FUSED variance + BN apply + hrelu + pre-for-conv2 ----------------
__global__ void bnva_kernel(const float* __restrict__ bias, const float* __restrict__ weight,
                            float scale) {
    __shared__ float sv[8];
    __shared__ int slast;
    int wid = threadIdx.x >> 5, lid = threadIdx.x & 31;
    int p0 = blockIdx.x * 64;
    float mu8[8];
#pragma unroll
    for (int j = 0; j < 8; j++) mu8[j] = g_mu[lid*8 + j];
    float mu2 = g_sc[0];
    float acc = 0.f;
    for (int i = 0; i < 8; i++)
        acc += var_pixel(p0 + wid*8 + i, mu8, mu2);
    if (lid == 0) sv[wid] = acc;
    __syncthreads();
    if (threadIdx.x == 0) {
        float s = 0.f;
        for (int w = 0; w < 8; w++) s += sv[w];
        g_pv[blockIdx.x] = s;
        __threadfence();
        slast = (atomicAdd(&g_ctr, 1) == 255);
    }
    __syncthreads();
    if (slast) {
        float v = g_pv[threadIdx.x];
        __shared__ float sb[8];
        float r[1] = { v };
        blockReduceK<1>(r, sb);
        if (threadIdx.x == 0) {
            float var = r[0] / 16384.0f;
            g_ctr = 0;
            __threadfence();
            ((volatile float*)g_sc)[5] = sqrtf(weight[0] / fmaxf(var, EPSF));
        }
    }
    if (threadIdx.x == 0) {
        volatile float* vs = g_sc;
        while (vs[5] == 0.f) { }
    }
    __syncthreads();
    float b8[8];
#pragma unroll
    for (int j = 0; j < 8; j++) b8[j] = bias[lid*8 + j];
    for (int i = 0; i < 8; i++) {
        int p = p0 + wid*8 + i;
        const float4* row = (const float4*)(g_h + (size_t)p*256 + lid*8);
        float4 a = row[0], cc = row[1];
        float xv[8] = {a.x,a.y,a.z,a.w,cc.x,cc.y,cc.z,cc.w};
        float hc[8];
        float nh = bn_point_w(xv, mu8, b8, hc);
        float lf = atanhf(fminf(nh, CLIP1)) / nh;
        float rc[8];
        float q = 0.f;
#pragma unroll
        for (int k = 0; k < 8; k++) { rc[k] = fmaxf(lf*hc[k], 0.f); q += rc[k]*rc[k]; }
        float rs = warpSum(q);
        float nr = sqrtf(fmaxf(rs, EPSF));
        float ef = tanhf(nr) / nr;
        float nhr = sqrtf(fmaxf(ef*ef*rs, EPSF));
        float adj = 1.0f;
        if (nhr > MAXN) { adj = MAXN/nhr; nhr = MAXN; }
        float f3 = atanhf(fminf(nhr, CLIP1)) / nhr * scale;
        float g = f3 * ef * adj;
        float4 o0 = make_float4(g*rc[0], g*rc[1], g*rc[2], g*rc[3]);
        float4 o1 = make_float4(g*rc[4], g*rc[5], g*rc[6], g*rc[7]);
        float* dst = g_v + (size_t)p*256 + lid*8;
        *(float4*)dst = o0;
        *(float4*)(dst + 4) = o1;
        if (lid == 0) g_q2[p] = f3*f3*nhr*nhr;
    }
}

// ---------------- FUSED variance + BN2 apply + residual + hrelu + NCHW out ----------------
__global__ void bnvf_kernel(const float* __restrict__ bias, const float* __restrict__ weight,
                            float* __restrict__ out) {
    __shared__ float so[256][33];
    __shared__ float sv[8];
    __shared__ int slast;
    int tid = threadIdx.x, lane = tid & 31, w8 = tid >> 5;
    int p0 = blockIdx.x * 32;
    int b = p0 >> 10, hw0 = p0 & 1023;
    float mu8[8], b8[8];
#pragma unroll
    for (int j = 0; j < 8; j++) { mu8[j] = g_mu[lane*8 + j]; b8[j] = bias[lane*8 + j]; }
    float mu2 = g_sc[0];
    float acc = 0.f;
    for (int i = 0; i < 4; i++)
        acc += var_pixel(p0 + w8*4 + i, mu8, mu2);
    if (lane == 0) sv[w8] = acc;
    __syncthreads();
    if (tid == 0) {
        float s = 0.f;
        for (int w = 0; w < 8; w++) s += sv[w];
        g_pv[blockIdx.x] = s;
        __threadfence();
        slast = (atomicAdd(&g_ctr, 1) == 511);
    }
    __syncthreads();
    if (slast) {
        float v = g_pv[tid] + g_pv[tid + 256];
        __shared__ float sb[8];
        float r[1] = { v };
        blockReduceK<1>(r, sb);
        if (tid == 0) {
            float var = r[0] / 16384.0f;
            g_ctr = 0;
            __threadfence();
            ((volatile float*)g_sc)[5] = sqrtf(weight[0] / fmaxf(var, EPSF));
        }
    }
    if (tid == 0) {
        volatile float* vs = g_sc;
        while (vs[5] == 0.f) { }
    }
    __syncthreads();
#pragma unroll
    for (int pp = 0; pp < 4; pp++) {
        int pl = w8*4 + pp;
        int p = p0 + pl;
        const float4* row = (const float4*)(g_h + (size_t)p*256 + lane*8);
        float4 a = row[0], cc = row[1];
        float xv[8] = {a.x,a.y,a.z,a.w,cc.x,cc.y,cc.z,cc.w};
        float hc[8];
        float nh = bn_point_w(xv, mu8, b8, hc);
        const float4* rrow = (const float4*)(g_xl + (size_t)p*256 + lane*8);
        float4 r0 = rrow[0], r1 = rrow[1];
        float res[8] = {r0.x,r0.y,r0.z,r0.w,r1.x,r1.y,r1.z,r1.w};
        float q1 = 0.f, q2 = 0.f;
#pragma unroll
        for (int i = 0; i < 8; i++) { q1 += res[i]*res[i]; q2 += hc[i]*res[i]; }
        float y2 = warpSum(q1), xy = warpSum(q2);
        float x2 = nh*nh;
        float A4 = 1.0f + 2.0f*xy + y2, B4 = 1.0f - x2;
        float den4 = fmaxf(1.0f + 2.0f*xy + x2*y2, EPSF);
        float hm[8];
#pragma unroll
        for (int i = 0; i < 8; i++) hm[i] = (A4*hc[i] + B4*res[i]) / den4;
        float nm2 = fmaxf(A4*A4*x2 + 2.0f*A4*B4*xy + B4*B4*y2, 0.f) / (den4*den4);
        float nmv = sqrtf(fmaxf(nm2, EPSF));
        float lf = atanhf(fminf(nmv, CLIP1)) / nmv;
        float rc[8];
        float q = 0.f;
#pragma unroll
        for (int i = 0; i < 8; i++) { rc[i] = fmaxf(lf*hm[i], 0.f); q += rc[i]*rc[i]; }
        float rs = warpSum(q);
        float nr = sqrtf(fmaxf(rs, EPSF));
        float ef = tanhf(nr) / nr;
        float nhr = sqrtf(fmaxf(ef*ef*rs, EPSF));
        float adj = (nhr > MAXN) ? MAXN/nhr : 1.0f;
#pragma unroll
        for (int i = 0; i < 8; i++) so[lane*8 + i][pl] = ef * adj * rc[i];
    }
    __syncthreads();
#pragma unroll 8
    for (int i = 0; i < 32; i++) {
        int c = i*8 + w8;
        out[(size_t)(b*256 + c)*1024 + hw0 + lane] = so[c][lane];
    }
}

// ---------------- launcher ----------------
extern "C" void kernel_launch(void* const* d_in, const int* in_sizes, int n_in,
                              void* d_out, int out_size) {
    const float* x  = (const float*)d_in[0];
    const float* z1 = (const float*)d_in[1];
    const float* z2 = (const float*)d_in[2];
    const float* w1 = (const float*)d_in[3];
    const float* b1 = (const float*)d_in[4];
    const float* w2 = (const float*)d_in[5];
    const float* b2 = (const float*)d_in[6];
    float* out = (float*)d_out;

    // scale = Beta(1152, 0.5) / Beta(128, 0.5)
    double lg = lgamma(1152.0) - lgamma(1152.5) - lgamma(128.0) + lgamma(128.5);
    float scale = (float)exp(lg);

    static int smem_set = 0;
    if (!smem_set) {
        cudaFuncSetAttribute(wino_gemm, cudaFuncAttributeMaxDynamicSharedMemorySize, CONV_SMEM);
        smem_set = 1;
    }

    dim3 ggrid(8, 4, 36);

    wino_u<<<dim3(256, 2), 256>>>(z1, z2);       // 0
    pre2_kernel<<<PNUM/32, 256>>>(x, scale);     // 1
    wino_in<<<NTIL, 256>>>();                    // 2
    wino_gemm<<<ggrid, 256, CONV_SMEM>>>(0);     // 3  <- ncu capture target
    wino_out<<<NTIL, 256>>>(0);

    bnmu_kernel<<<8, 256>>>(b1);
    bnva_kernel<<<256, 256>>>(b1, w1, scale);

    wino_in<<<NTIL, 256>>>();
    wino_gemm<<<ggrid, 256, CONV_SMEM>>>(1);
    wino_out<<<NTIL, 256>>>(256);

    bnmu_kernel<<<8, 256>>>(b2);
    bnvf_kernel<<<512, 256>>>(b2, w2, out);
}

// round 15
// speedup vs baseline: 1.0888x; 1.0298x over previous
#include <cuda_runtime.h>
#include <cuda_bf16.h>
#include <math.h>
#include <stdint.h>

// Problem constants: B=16, C=256, H=W=32
#define PNUM 16384
#define CNUM 256
#define CLIP1 0.9999999f
#define MAXN  0.99999f
#define EPSF  1e-15f

#define NPOS 36
#define NTIL 1024
#define STAGE_BYTES 24576u       // Ahi 8K + Alo 8K + Bhi 4K + Blo 4K
#define CONV_SMEM (3*24576)      // 72 KB -> 3 CTAs/SM

// ---------------- device scratch ----------------
__device__ __align__(16) float g_v [PNUM*CNUM];
__device__ __align__(16) __nv_bfloat16 g_Vhi[NPOS*NTIL*CNUM];
__device__ __align__(16) __nv_bfloat16 g_Vlo[NPOS*NTIL*CNUM];
__device__ __align__(16) __nv_bfloat16 g_uhi1[NPOS*CNUM*CNUM];
__device__ __align__(16) __nv_bfloat16 g_ulo1[NPOS*CNUM*CNUM];
__device__ __align__(16) __nv_bfloat16 g_uhi2[NPOS*CNUM*CNUM];
__device__ __align__(16) __nv_bfloat16 g_ulo2[NPOS*CNUM*CNUM];
__device__ __align__(16) float g_m [NPOS*NTIL*CNUM];
__device__ __align__(16) float g_h [PNUM*CNUM];   // NORMALIZED h (post FC)
__device__ __align__(16) float g_xl[PNUM*CNUM];
__device__ float g_q2[PNUM];
__device__ float g_zn[512];
__device__ float g_pm [NTIL*CNUM];
__device__ float g_pm2[8*CNUM];
__device__ float g_pd[NTIL];
__device__ float g_pv[512];
__device__ float g_mu[CNUM];
__device__ float g_sc[8];
__device__ int   g_ctr  = 0;
__device__ int   g_ctr2 = 0;

// ---------------- PTX helpers ----------------
__device__ __forceinline__ uint32_t smem_u32(const void* p) {
    uint32_t a;
    asm("{ .reg .u64 t; cvta.to.shared.u64 t, %1; cvt.u32.u64 %0, t; }" : "=r"(a) : "l"(p));
    return a;
}
__device__ __forceinline__ void cpa16(uint32_t dst, const void* src) {
    asm volatile("cp.async.cg.shared.global [%0], [%1], 16;" :: "r"(dst), "l"(src) : "memory");
}
__device__ __forceinline__ void cp_commit() {
    asm volatile("cp.async.commit_group;" ::: "memory");
}
template<int N>
__device__ __forceinline__ void cp_wait() {
    asm volatile("cp.async.wait_group %0;" :: "n"(N) : "memory");
}
__device__ __forceinline__ void ldsm4(uint32_t* r, uint32_t addr) {
    asm volatile("ldmatrix.sync.aligned.m8n8.x4.shared.b16 {%0,%1,%2,%3}, [%4];"
        : "=r"(r[0]), "=r"(r[1]), "=r"(r[2]), "=r"(r[3]) : "r"(addr));
}
__device__ __forceinline__ void mma16816(float* d, const uint32_t* a, const uint32_t* b) {
    asm volatile("mma.sync.aligned.m16n8k16.row.col.f32.bf16.bf16.f32 "
        "{%0,%1,%2,%3}, {%4,%5,%6,%7}, {%8,%9}, {%0,%1,%2,%3};"
        : "+f"(d[0]), "+f"(d[1]), "+f"(d[2]), "+f"(d[3])
        : "r"(a[0]), "r"(a[1]), "r"(a[2]), "r"(a[3]), "r"(b[0]), "r"(b[1]));
}
__device__ __forceinline__ uint32_t swz(int r, int c) {
    return (uint32_t)(((r >> 1) << 7) | (((((r & 1) << 2) | c) ^ ((r >> 1) & 7)) << 4));
}

// ---------------- reductions ----------------
__device__ __forceinline__ float warpSum(float v) {
#pragma unroll
    for (int o = 16; o > 0; o >>= 1) v += __shfl_xor_sync(0xffffffffu, v, o);
    return v;
}
template<int K>
__device__ __forceinline__ void blockReduceK(float* v, float* sbuf) {
    int tid = threadIdx.x, lane = tid & 31, wid = tid >> 5;
#pragma unroll
    for (int i = 0; i < K; i++) {
        float x = v[i];
#pragma unroll
        for (int o = 16; o > 0; o >>= 1) x += __shfl_down_sync(0xffffffffu, x, o);
        if (lane == 0) sbuf[i*8 + wid] = x;
    }
    __syncthreads();
    if (tid == 0) {
#pragma unroll
        for (int i = 0; i < K; i++) {
            float s = sbuf[i*8];
            for (int w = 1; w < 8; w++) s += sbuf[i*8 + w];
            sbuf[i*8] = s;
        }
    }
    __syncthreads();
#pragma unroll
    for (int i = 0; i < K; i++) v[i] = sbuf[i*8];
    __syncthreads();
}

// ---------------- Winograd transforms ----------------
__device__ __forceinline__ void bt6(const float* in, float* out) {
    out[0] =  4.f*in[0] - 5.f*in[2] + in[4];
    out[1] = -4.f*in[1] - 4.f*in[2] + in[3] + in[4];
    out[2] =  4.f*in[1] - 4.f*in[2] - in[3] + in[4];
    out[3] = -2.f*in[1] -     in[2] + 2.f*in[3] + in[4];
    out[4] =  2.f*in[1] -     in[2] - 2.f*in[3] + in[4];
    out[5] =  4.f*in[1] - 5.f*in[3] + in[5];
}
__device__ __forceinline__ void g6(const float* in, float* out) {
    out[0] = 0.25f*in[0];
    out[1] = -(in[0] + in[1] + in[2]) * (1.f/6.f);
    out[2] = (-in[0] + in[1] - in[2]) * (1.f/6.f);
    out[3] = in[0]*(1.f/24.f) + in[1]*(1.f/12.f) + in[2]*(1.f/6.f);
    out[4] = in[0]*(1.f/24.f) - in[1]*(1.f/12.f) + in[2]*(1.f/6.f);
    out[5] = in[2];
}
__device__ __forceinline__ void at6(const float* in, float* out) {
    out[0] = in[0] + in[1] + in[2] + in[3] + in[4];
    out[1] = in[1] - in[2] + 2.f*(in[3] - in[4]);
    out[2] = in[1] + in[2] + 4.f*(in[3] + in[4]);
    out[3] = in[1] - in[2] + 8.f*(in[3] - in[4]) + in[5];
}

// ---------------- U = G z G^T (+ fused z column norms), both weight sets ----------------
__global__ void wino_u(const float* __restrict__ z1, const float* __restrict__ z2) {
    __shared__ float sb[8];
    const float* z = blockIdx.y ? z2 : z1;
    __nv_bfloat16* uh = blockIdx.y ? g_uhi2 : g_uhi1;
    __nv_bfloat16* ul = blockIdx.y ? g_ulo2 : g_ulo1;
    int co = blockIdx.x, ci = threadIdx.x;
    float g[3][3];
    float nsum = 0.f;
#pragma unroll
    for (int i = 0; i < 3; i++)
#pragma unroll
        for (int j = 0; j < 3; j++) {
            float w = z[(size_t)((i*3 + j)*256 + ci)*256 + co];
            g[i][j] = w;
            nsum += w*w;
        }
    float r1[1] = { nsum };
    blockReduceK<1>(r1, sb);
    if (ci == 0) g_zn[blockIdx.y*256 + co] = sqrtf(fmaxf(r1[0], EPSF));

    float t[6][3];
#pragma unroll
    for (int j = 0; j < 3; j++) {
        float in[3] = { g[0][j], g[1][j], g[2][j] };
        float out[6];
        g6(in, out);
#pragma unroll
        for (int a = 0; a < 6; a++) t[a][j] = out[a];
    }
#pragma unroll
    for (int a = 0; a < 6; a++) {
        float out[6];
        g6(t[a], out);
#pragma unroll
        for (int b = 0; b < 6; b++) {
            float u = out[b];
            __nv_bfloat16 hi = __float2bfloat16(u);
            size_t idx = ((size_t)((a*6 + b)*256 + co))*256 + ci;
            uh[idx] = hi;
            ul[idx] = __float2bfloat16(u - __bfloat162float(hi));
        }
    }
}

// ---------------- V = B^T d B per tile ----------------
__global__ void wino_in() {
    int t = blockIdx.x, ci = threadIdx.x;
    int b = t >> 6, tr = (t >> 3) & 7, tc = t & 7;
    int base = b << 10;
    float d[6][6];
#pragma unroll
    for (int y = 0; y < 6; y++) {
        int iy = 4*tr - 1 + y;
#pragma unroll
        for (int x = 0; x < 6; x++) {
            int ix = 4*tc - 1 + x;
            bool ok = ((unsigned)iy < 32u) && ((unsigned)ix < 32u);
            d[y][x] = ok ? g_v[(size_t)(base + iy*32 + ix)*256 + ci] : 0.f;
        }
    }
    float e[6][6];
#pragma unroll
    for (int x = 0; x < 6; x++) {
        float in[6] = { d[0][x], d[1][x], d[2][x], d[3][x], d[4][x], d[5][x] };
        float out[6];
        bt6(in, out);
#pragma unroll
        for (int a = 0; a < 6; a++) e[a][x] = out[a];
    }
#pragma unroll
    for (int a = 0; a < 6; a++) {
        float out[6];
        bt6(e[a], out);
#pragma unroll
        for (int bb = 0; bb < 6; bb++) {
            float v = out[bb];
            __nv_bfloat16 hi = __float2bfloat16(v);
            size_t idx = ((size_t)((a*6 + bb)*NTIL + t))*256 + ci;
            g_Vhi[idx] = hi;
            g_Vlo[idx] = __float2bfloat16(v - __bfloat162float(hi));
        }
    }
}

// ---------------- batched Winograd GEMM (proven R11/R12 shape) ----------------
__global__ void __launch_bounds__(256, 3) wino_gemm(int which) {
    extern __shared__ __align__(16) char dsm[];
    uint32_t sbase = smem_u32(dsm);

    const __nv_bfloat16* Bh = which ? g_uhi2 : g_uhi1;
    const __nv_bfloat16* Bl = which ? g_ulo2 : g_ulo1;
    int t0  = blockIdx.x << 7;
    int nq  = blockIdx.y;
    int pos = blockIdx.z;

    int tid = threadIdx.x, wid = tid >> 5, l = tid & 31;

    int c4 = tid & 3;
    int r0 = tid >> 2;
    uint32_t ph0 = swz(r0, c4), ph1 = swz(r0 + 64, c4);
    const __nv_bfloat16* Abase_hi = g_Vhi + ((size_t)pos*NTIL + t0)*256;
    const __nv_bfloat16* Abase_lo = g_Vlo + ((size_t)pos*NTIL + t0)*256;
    const __nv_bfloat16* Bbase_hi = Bh + ((size_t)pos*256 + nq*64)*256;
    const __nv_bfloat16* Bbase_lo = Bl + ((size_t)pos*256 + nq*64)*256;
    size_t a0 = (size_t)r0*256 + c4*8, a1 = (size_t)(r0 + 64)*256 + c4*8;

    int m0 = (wid & 3) << 5;
    int n0w = (wid >> 2) << 5;
    int mi = l >> 3;
    int rA = m0 + ((mi & 1) << 3) + (l & 7);
    uint32_t qA0 = swz(rA, mi >> 1);
    int rB = n0w + (((mi >> 1) & 1) << 3) + (l & 7);
    uint32_t qB0 = swz(rB, mi & 1);

    float acc[2][4][4];
#pragma unroll
    for (int i = 0; i < 2; i++)
#pragma unroll
        for (int j = 0; j < 4; j++)
#pragma unroll
            for (int k = 0; k < 4; k++) acc[i][j][k] = 0.f;

    auto load_chunk = [&](int kc, int stage) {
        size_t coff = (size_t)(kc << 5);
        uint32_t st = sbase + (uint32_t)stage*STAGE_BYTES;
        cpa16(st + ph0,         Abase_hi + a0 + coff);
        cpa16(st + 8192 + ph0,  Abase_lo + a0 + coff);
        cpa16(st + ph1,         Abase_hi + a1 + coff);
        cpa16(st + 8192 + ph1,  Abase_lo + a1 + coff);
        cpa16(st + 16384 + ph0, Bbase_hi + a0 + coff);
        cpa16(st + 20480 + ph0, Bbase_lo + a0 + coff);
        cp_commit();
    };

    load_chunk(0, 0);
    load_chunk(1, 1);

    for (int kc = 0; kc < 8; kc++) {
        int stage = kc % 3;
        if (kc < 6) cp_wait<1>(); else cp_wait<0>();
        __syncthreads();
        if (kc + 2 < 8) load_chunk(kc + 2, (kc + 2) % 3);

        uint32_t st = sbase + (uint32_t)stage*STAGE_BYTES;
        uint32_t Ahi = st, Alo = st + 8192, Bhi = st + 16384, Blo = st + 20480;
#pragma unroll
        for (int ks = 0; ks < 2; ks++) {
            uint32_t kx = (uint32_t)(ks << 5);
            uint32_t qa = qA0 ^ kx, qb = qB0 ^ kx;
            uint32_t ah[8], al[8], bbv[8];
            ldsm4(bbv,     Bhi + qb);
            ldsm4(bbv + 4, Bhi + qb + 1024);
            ldsm4(ah,     Ahi + qa);
            ldsm4(ah + 4, Ahi + qa + 1024);
            ldsm4(al,     Alo + qa);
            ldsm4(al + 4, Alo + qa + 1024);
#pragma unroll
            for (int nf = 0; nf < 4; nf++) {
                const uint32_t* bp = bbv + nf*2;
                mma16816(acc[0][nf], ah,     bp);
                mma16816(acc[1][nf], ah + 4, bp);
            }
#pragma unroll
            for (int nf = 0; nf < 4; nf++) {
                const uint32_t* bp = bbv + nf*2;
                mma16816(acc[0][nf], al,     bp);
                mma16816(acc[1][nf], al + 4, bp);
            }
            ldsm4(bbv,     Blo + qb);
            ldsm4(bbv + 4, Blo + qb + 1024);
#pragma unroll
            for (int nf = 0; nf < 4; nf++) {
                const uint32_t* bp = bbv + nf*2;
                mma16816(acc[0][nf], ah,     bp);
                mma16816(acc[1][nf], ah + 4, bp);
            }
        }
    }

    int row0 = m0 + (l >> 2);
    int col0 = n0w + ((l & 3) << 1);
    float* gm = g_m + ((size_t)pos*NTIL + t0)*256 + nq*64;
#pragma unroll
    for (int mf = 0; mf < 2; mf++)
#pragma unroll
        for (int hf = 0; hf < 2; hf++) {
            int r = row0 + mf*16 + hf*8;
            float* rowp = gm + (size_t)r*256;
#pragma unroll
            for (int nf = 0; nf < 4; nf++)
                *(float2*)(rowp + col0 + nf*8) =
                    make_float2(acc[mf][nf][hf*2], acc[mf][nf][hf*2 + 1]);
        }
}

// ---------------- pre2 (+ fused xT) ----------------
__global__ void pre2_kernel(const float* __restrict__ x, float scale) {
    __shared__ float sx[256][33];
    int tid = threadIdx.x, lane = tid & 31, w8 = tid >> 5;
    int p0 = blockIdx.x * 32;
    int b = p0 >> 10, hw0 = p0 & 1023;
#pragma unroll 8
    for (int i = 0; i < 32; i++) {
        int c = i*8 + w8;
        sx[c][lane] = x[(size_t)(b*256 + c)*1024 + hw0 + lane];
    }
    __syncthreads();
#pragma unroll 8
    for (int pl = 0; pl < 32; pl++)
        g_xl[(size_t)(p0 + pl)*256 + tid] = sx[tid][pl];
#pragma unroll
    for (int pp = 0; pp < 4; pp++) {
        int pl = w8*4 + pp;
        int p = p0 + pl;
        float xv[8];
#pragma unroll
        for (int i = 0; i < 8; i++) xv[i] = sx[lane*8 + i][pl];
        float q = 0.f;
#pragma unroll
        for (int i = 0; i < 8; i++) q += xv[i]*xv[i];
        float n2 = warpSum(q);
        float n = sqrtf(fmaxf(n2, EPSF));
        float f = atanhf(fminf(n, CLIP1)) / n * scale;
        float4 o0 = make_float4(f*xv[0], f*xv[1], f*xv[2], f*xv[3]);
        float4 o1 = make_float4(f*xv[4], f*xv[5], f*xv[6], f*xv[7]);
        float* dst = g_v + (size_t)p*256 + lane*8;
        *(float4*)dst = o0;
        *(float4*)(dst + 4) = o1;
        if (lane == 0) g_q2[p] = f*f*n2;
    }
}

// ---------------- per-pixel s ----------------
__device__ __forceinline__ float s_from_q2(int p) {
    int h = (p >> 5) & 31, w = p & 31;
    float np2 = 0.f;
#pragma unroll
    for (int dy = -1; dy <= 1; dy++)
#pragma unroll
        for (int dx = -1; dx <= 1; dx++) {
            int sh = h + dy, sw = w + dx;
            if ((unsigned)sh < 32u && (unsigned)sw < 32u) np2 += g_q2[p + dy*32 + dx];
        }
    float np = sqrtf(fmaxf(np2, EPSF));
    float th = tanhf(np);
    float uf = th / np;
    float un = th;
    if (un > MAXN) { uf *= MAXN/un; un = MAXN; }
    float lam = 2.0f / fmaxf(1.0f - un*un, EPSF);
    return lam * uf;
}

// ---------------- output transform + FC + BN partials; writes NORMALIZED h ----------------
// fast path: sinh(a*asinh(t)) = 0.5*(exp(a*u) - exp(-a*u)), u = log(t + sqrt(t^2+1))
// (two __expf, NO division — R14's 1/e division was the regression)
__global__ void wino_out(int znoff) {
    __shared__ float ss[16];
    __shared__ float slam[16];
    __shared__ float sld[16];
    __shared__ float sinv[16];
    __shared__ float ybuf[16][260];
    int t = blockIdx.x, co = threadIdx.x;
    int b = t >> 6, tr = (t >> 3) & 7, tc = t & 7;
    int prow = (b << 10) + (4*tr)*32 + 4*tc;
    if (co < 16) {
        int r = co >> 2, c = co & 3;
        ss[co] = s_from_q2(prow + r*32 + c);
    }
    float m[36];
#pragma unroll
    for (int pos = 0; pos < 36; pos++)
        m[pos] = g_m[((size_t)pos*NTIL + t)*256 + co];
    float Z[4][6];
#pragma unroll
    for (int bb = 0; bb < 6; bb++) {
        float in[6] = { m[bb], m[6+bb], m[12+bb], m[18+bb], m[24+bb], m[30+bb] };
        float out[4];
        at6(in, out);
#pragma unroll
        for (int r = 0; r < 4; r++) Z[r][bb] = out[r];
    }
    float zn = g_zn[znoff + co];
    float izn = 1.0f / zn;
    float a2 = 2.0f * zn;
    __syncthreads();
#pragma unroll
    for (int r = 0; r < 4; r++) {
        float Y[4];
        at6(Z[r], Y);
#pragma unroll
        for (int c = 0; c < 4; c++) {
            float s = ss[r*4 + c];
            float tt = Y[c] * s * izn;
            float w = tt + sqrtf(fmaf(tt, tt, 1.0f));
            float u = __logf(w);
            float au = a2 * u;
            ybuf[r*4 + c][co] = 0.5f * (__expf(au) - __expf(-au));
        }
    }
    __syncthreads();
    int wd = co >> 5, lid = co & 31;
#pragma unroll
    for (int k = 0; k < 2; k++) {
        int pl = wd*2 + k;
        float q = 0.f;
#pragma unroll
        for (int i = 0; i < 8; i++) {
            float v = ybuf[pl][lid*8 + i];
            q += v*v;
        }
        float tot = warpSum(q);
        float inv = 1.0f / (1.0f + sqrtf(1.0f + tot));
        float n2 = tot*inv*inv;
        float lam = 2.0f / fmaxf(1.0f - n2, EPSF);
        if (lid == 0) { slam[pl] = lam*inv; sld[pl] = lam - 1.0f; sinv[pl] = inv; }
    }
    __syncthreads();
    float accm = 0.f;
#pragma unroll
    for (int pl = 0; pl < 16; pl++)
        accm += slam[pl] * ybuf[pl][co];
    g_pm[t*256 + co] = accm;
    if (co == 0) {
        float d = 0.f;
#pragma unroll
        for (int pl = 0; pl < 16; pl++) d += sld[pl];
        g_pd[t] = d;
    }
#pragma unroll
    for (int pl = 0; pl < 16; pl++) {
        int p = prow + (pl >> 2)*32 + (pl & 3);
        g_h[(size_t)p*256 + co] = ybuf[pl][co] * sinv[pl];
    }
}

// ---------------- BN mu: 8-block partial sum + last-block finalize ----------------
__global__ void bnmu_kernel(const float* __restrict__ bias) {
    __shared__ float sb[24];
    __shared__ int slast;
    int c = threadIdx.x;
    float s = 0.f;
    int g0 = blockIdx.x * 128;
    for (int g = 0; g < 128; g++) s += g_pm[(g0 + g)*256 + c];
    g_pm2[blockIdx.x*256 + c] = s;
    __threadfence();
    if (c == 0) slast = (atomicAdd(&g_ctr2, 1) == 7);
    __syncthreads();
    if (!slast) return;
    __threadfence();
    float msum = 0.f;
#pragma unroll
    for (int j = 0; j < 8; j++) msum += g_pm2[j*256 + c];
    float dv = 0.f;
#pragma unroll
    for (int j = 0; j < 4; j++) dv += g_pd[j*256 + c];
    float r1[1] = { dv };
    blockReduceK<1>(r1, sb);
    float den = fmaxf(r1[0], EPSF);
    float m = msum / den;
    float r2[1] = { m*m };
    blockReduceK<1>(r2, sb);
    float nm = sqrtf(fmaxf(r2[0], EPSF));
    float fac = tanhf(0.5f * atanhf(fminf(nm, CLIP1))) / nm;
    float muc = fac * m;
    g_mu[c] = muc;
    float bc = bias[c];
    float r3[3] = { muc*muc, bc*bc, bc*muc };
    blockReduceK<3>(r3, sb);
    if (c == 0) {
        float mu2 = r3[0], b2 = r3[1], bm = r3[2];
        g_sc[0] = mu2;
        g_sc[1] = 2.0f / fmaxf(1.0f - mu2, EPSF);
        g_sc[2] = b2;
        g_sc[3] = 2.0f / fmaxf(1.0f - b2, EPSF);
        g_sc[4] = bm;
        ((volatile float*)g_sc)[5] = 0.f;
        g_ctr2 = 0;
    }
}

// ---------------- variance partial (normalized input) ----------------
__device__ __forceinline__ float var_pixel(int p, const float* mu8, float mu2) {
    int lid = threadIdx.x & 31;
    const float4* row = (const float4*)(g_h + (size_t)p*256 + lid*8);
    float4 a = row[0], cc = row[1];
    float v[8] = {a.x,a.y,a.z,a.w,cc.x,cc.y,cc.z,cc.w};
    float q1 = 0.f, q2 = 0.f;
#pragma unroll
    for (int j = 0; j < 8; j++) { q1 += v[j]*v[j]; q2 += v[j]*mu8[j]; }
    float xp2 = warpSum(q1);
    float ip  = warpSum(q2);
    float A = 1.0f - 2.0f*ip + mu2;
    float B = 1.0f - xp2;
    float nn = fmaxf(A*A*xp2 - 2.0f*A*B*ip + B*B*mu2, 0.f);
    float den = fmaxf(1.0f - 2.0f*ip + xp2*mu2, EPSF);
    float nr = sqrtf(fmaxf(nn/(den*den), EPSF));
    float dd = 2.0f * atanhf(fminf(nr, CLIP1));
    return dd*dd;
}

// ---------------- shared BN point transform ----------------
__device__ __forceinline__ float bn_point_w(const float* xv, const float* mu8, const float* b8,
                                            float* hc) {
    float mu2 = g_sc[0], lam_mu = g_sc[1], b2 = g_sc[2], lam_b = g_sc[3],
          bm = g_sc[4], rstd = g_sc[5];
    float s0 = 0.f, s1 = 0.f, s2 = 0.f;
#pragma unroll
    for (int i = 0; i < 8; i++) { s0 += xv[i]*xv[i]; s1 += mu8[i]*xv[i]; s2 += b8[i]*xv[i]; }
    float xp2 = warpSum(s0), ip = warpSum(s1), bx = warpSum(s2);
    float A  = 1.0f - 2.0f*ip + xp2;
    float Bc = 1.0f - mu2;
    float den = fmaxf(1.0f - 2.0f*ip + mu2*xp2, EPSF);
    float nd2 = fmaxf(A*A*mu2 - 2.0f*A*Bc*ip + Bc*Bc*xp2, 0.f) / (den*den);
    float nd = sqrtf(fmaxf(nd2, EPSF));
    float cv = (2.0f/lam_mu) * atanhf(fminf(nd, CLIP1)) / nd;
    float uw = cv * (Bc*bx - A*bm) / den;
    float vw = cv * (A*mu2 - Bc*ip) / den;
    float av  = -uw*mu2 - vw - 2.0f*bm*vw;
    float bv2 = -vw*b2 + uw;
    float dgy = fmaxf(1.0f - 2.0f*bm + b2*mu2, EPSF);
    float fac = (lam_mu / lam_b) * rstd;
    float uc[8];
    float t0 = 0.f, t1 = 0.f;
#pragma unroll
    for (int i = 0; i < 8; i++) {
        float vc = cv * (Bc*xv[i] - A*mu8[i]) / den;
        uc[i] = (vc + 2.0f*(av*b8[i] - bv2*mu8[i]) / dgy) * fac;
        t0 += uc[i]*uc[i];
        t1 += b8[i]*uc[i];
    }
    float u2 = warpSum(t0), bu = warpSum(t1);
    float nu = sqrtf(fmaxf(u2, EPSF));
    float tf = tanhf(0.5f * lam_b * nu) / nu;
    float s2m = tf*tf*u2;
    float bs  = tf*bu;
    float A3 = 1.0f + 2.0f*bs + s2m, B3 = 1.0f - b2;
    float den3 = fmaxf(1.0f + 2.0f*bs + b2*s2m, EPSF);
#pragma unroll
    for (int i = 0; i < 8; i++) hc[i] = (A3*b8[i] + B3*tf*uc[i]) / den3;
    float nh2 = fmaxf(A3*A3*b2 + 2.0f*A3*B3*bs + B3*B3*s2m, 0.f) / (den3*den3);
    float nh = sqrtf(fmaxf(nh2, EPSF));
    if (nh > MAXN) {
        float q = MAXN / nh;
#pragma unroll
        for (int i = 0; i < 8; i++) hc[i] *= q;
        nh = MAXN;
    }
    return nh;
}

// ---------------- FUSED variance + BN apply + hrelu + pre-for-conv2 ----------------
__global__ void bnva_kernel(const float* __restrict__ bias, const float* __restrict__ weight,
                            float scale) {
    __shared__ float sv[8];
    __shared__ int slast;
    int wid = threadIdx.x >> 5, lid = threadIdx.x & 31;
    int p0 = blockIdx.x * 64;
    float mu8[8];
#pragma unroll
    for (int j = 0; j < 8; j++) mu8[j] = g_mu[lid*8 + j];
    float mu2 = g_sc[0];
    float acc = 0.f;
    for (int i = 0; i < 8; i++)
        acc += var_pixel(p0 + wid*8 + i, mu8, mu2);
    if (lid == 0) sv[wid] = acc;
    __syncthreads();
    if (threadIdx.x == 0) {
        float s = 0.f;
        for (int w = 0; w < 8; w++) s += sv[w];
        g_pv[blockIdx.x] = s;
        __threadfence();
        slast = (atomicAdd(&g_ctr, 1) == 255);
    }
    __syncthreads();
    if (slast) {
        float v = g_pv[threadIdx.x];
        __shared__ float sb[8];
        float r[1] = { v };
        blockReduceK<1>(r, sb);
        if (threadIdx.x == 0) {
            float var = r[0] / 16384.0f;
            g_ctr = 0;
            __threadfence();
            ((volatile float*)g_sc)[5] = sqrtf(weight[0] / fmaxf(var, EPSF));
        }
    }
    if (threadIdx.x == 0) {
        volatile float* vs = g_sc;
        while (vs[5] == 0.f) { }
    }
    __syncthreads();
    float b8[8];
#pragma unroll
    for (int j = 0; j < 8; j++) b8[j] = bias[lid*8 + j];
    for (int i = 0; i < 8; i++) {
        int p = p0 + wid*8 + i;
        const float4* row = (const float4*)(g_h + (size_t)p*256 + lid*8);
        float4 a = row[0], cc = row[1];
        float xv[8] = {a.x,a.y,a.z,a.w,cc.x,cc.y,cc.z,cc.w};
        float hc[8];
        float nh = bn_point_w(xv, mu8, b8, hc);
        float lf = atanhf(fminf(nh, CLIP1)) / nh;
        float rc[8];
        float q = 0.f;
#pragma unroll
        for (int k = 0; k < 8; k++) { rc[k] = fmaxf(lf*hc[k], 0.f); q += rc[k]*rc[k]; }
        float rs = warpSum(q);
        float nr = sqrtf(fmaxf(rs, EPSF));
        float ef = tanhf(nr) / nr;
        float nhr = sqrtf(fmaxf(ef*ef*rs, EPSF));
        float adj = 1.0f;
        if (nhr > MAXN) { adj = MAXN/nhr; nhr = MAXN; }
        float f3 = atanhf(fminf(nhr, CLIP1)) / nhr * scale;
        float g = f3 * ef * adj;
        float4 o0 = make_float4(g*rc[0], g*rc[1], g*rc[2], g*rc[3]);
        float4 o1 = make_float4(g*rc[4], g*rc[5], g*rc[6], g*rc[7]);
        float* dst = g_v + (size_t)p*256 + lid*8;
        *(float4*)dst = o0;
        *(float4*)(dst + 4) = o1;
        if (lid == 0) g_q2[p] = f3*f3*nhr*nhr;
    }
}

// ---------------- FUSED variance + BN2 apply + residual + hrelu + NCHW out ----------------
__global__ void bnvf_kernel(const float* __restrict__ bias, const float* __restrict__ weight,
                            float* __restrict__ out) {
    __shared__ float so[256][33];
    __shared__ float sv[8];
    __shared__ int slast;
    int tid = threadIdx.x, lane = tid & 31, w8 = tid >> 5;
    int p0 = blockIdx.x * 32;
    int b = p0 >> 10, hw0 = p0 & 1023;
    float mu8[8], b8[8];
#pragma unroll
    for (int j = 0; j < 8; j++) { mu8[j] = g_mu[lane*8 + j]; b8[j] = bias[lane*8 + j]; }
    float mu2 = g_sc[0];
    float acc = 0.f;
    for (int i = 0; i < 4; i++)
        acc += var_pixel(p0 + w8*4 + i, mu8, mu2);
    if (lane == 0) sv[w8] = acc;
    __syncthreads();
    if (tid == 0) {
        float s = 0.f;
        for (int w = 0; w < 8; w++) s += sv[w];
        g_pv[blockIdx.x] = s;
        __threadfence();
        slast = (atomicAdd(&g_ctr, 1) == 511);
    }
    __syncthreads();
    if (slast) {
        float v = g_pv[tid] + g_pv[tid + 256];
        __shared__ float sb[8];
        float r[1] = { v };
        blockReduceK<1>(r, sb);
        if (tid == 0) {
            float var = r[0] / 16384.0f;
            g_ctr = 0;
            __threadfence();
            ((volatile float*)g_sc)[5] = sqrtf(weight[0] / fmaxf(var, EPSF));
        }
    }
    if (tid == 0) {
        volatile float* vs = g_sc;
        while (vs[5] == 0.f) { }
    }
    __syncthreads();
#pragma unroll
    for (int pp = 0; pp < 4; pp++) {
        int pl = w8*4 + pp;
        int p = p0 + pl;
        const float4* row = (const float4*)(g_h + (size_t)p*256 + lane*8);
        float4 a = row[0], cc = row[1];
        float xv[8] = {a.x,a.y,a.z,a.w,cc.x,cc.y,cc.z,cc.w};
        float hc[8];
        float nh = bn_point_w(xv, mu8, b8, hc);
        const float4* rrow = (const float4*)(g_xl + (size_t)p*256 + lane*8);
        float4 r0 = rrow[0], r1 = rrow[1];
        float res[8] = {r0.x,r0.y,r0.z,r0.w,r1.x,r1.y,r1.z,r1.w};
        float q1 = 0.f, q2 = 0.f;
#pragma unroll
        for (int i = 0; i < 8; i++) { q1 += res[i]*res[i]; q2 += hc[i]*res[i]; }
        float y2 = warpSum(q1), xy = warpSum(q2);
        float x2 = nh*nh;
        float A4 = 1.0f + 2.0f*xy + y2, B4 = 1.0f - x2;
        float den4 = fmaxf(1.0f + 2.0f*xy + x2*y2, EPSF);
        float hm[8];
#pragma unroll
        for (int i = 0; i < 8; i++) hm[i] = (A4*hc[i] + B4*res[i]) / den4;
        float nm2 = fmaxf(A4*A4*x2 + 2.0f*A4*B4*xy + B4*B4*y2, 0.f) / (den4*den4);
        float nmv = sqrtf(fmaxf(nm2, EPSF));
        float lf = atanhf(fminf(nmv, CLIP1)) / nmv;
        float rc[8];
        float q = 0.f;
#pragma unroll
        for (int i = 0; i < 8; i++) { rc[i] = fmaxf(lf*hm[i], 0.f); q += rc[i]*rc[i]; }
        float rs = warpSum(q);
        float nr = sqrtf(fmaxf(rs, EPSF));
        float ef = tanhf(nr) / nr;
        float nhr = sqrtf(fmaxf(ef*ef*rs, EPSF));
        float adj = (nhr > MAXN) ? MAXN/nhr : 1.0f;
#pragma unroll
        for (int i = 0; i < 8; i++) so[lane*8 + i][pl] = ef * adj * rc[i];
    }
    __syncthreads();
#pragma unroll 8
    for (int i = 0; i < 32; i++) {
        int c = i*8 + w8;
        out[(size_t)(b*256 + c)*1024 + hw0 + lane] = so[c][lane];
    }
}

// ---------------- launcher ----------------
extern "C" void kernel_launch(void* const* d_in, const int* in_sizes, int n_in,
                              void* d_out, int out_size) {
    const float* x  = (const float*)d_in[0];
    const float* z1 = (const float*)d_in[1];
    const float* z2 = (const float*)d_in[2];
    const float* w1 = (const float*)d_in[3];
    const float* b1 = (const float*)d_in[4];
    const float* w2 = (const float*)d_in[5];
    const float* b2 = (const float*)d_in[6];
    float* out = (float*)d_out;

    // scale = Beta(1152, 0.5) / Beta(128, 0.5)
    double lg = lgamma(1152.0) - lgamma(1152.5) - lgamma(128.0) + lgamma(128.5);
    float scale = (float)exp(lg);

    static int smem_set = 0;
    if (!smem_set) {
        cudaFuncSetAttribute(wino_gemm, cudaFuncAttributeMaxDynamicSharedMemorySize, CONV_SMEM);
        smem_set = 1;
    }

    dim3 ggrid(8, 4, 36);

    wino_u<<<dim3(256, 2), 256>>>(z1, z2);       // 0
    pre2_kernel<<<PNUM/32, 256>>>(x, scale);     // 1
    wino_in<<<NTIL, 256>>>();                    // 2
    wino_gemm<<<ggrid, 256, CONV_SMEM>>>(0);     // 3  <- ncu capture target
    wino_out<<<NTIL, 256>>>(0);

    bnmu_kernel<<<8, 256>>>(b1);
    bnva_kernel<<<256, 256>>>(b1, w1, scale);

    wino_in<<<NTIL, 256>>>();
    wino_gemm<<<ggrid, 256, CONV_SMEM>>>(1);
    wino_out<<<NTIL, 256>>>(256);

    bnmu_kernel<<<8, 256>>>(b2);
    bnvf_kernel<<<512, 256>>>(b2, w2, out);
}

// round 16
// speedup vs baseline: 1.1157x; 1.0247x over previous
#include <cuda_runtime.h>
#include <cuda_bf16.h>
#include <math.h>
#include <stdint.h>

// Problem constants: B=16, C=256, H=W=32
#define PNUM 16384
#define CNUM 256
#define CLIP1 0.9999999f
#define MAXN  0.99999f
#define EPSF  1e-15f

#define NPOS 36
#define NTIL 1024
#define STAGE_BYTES 24576u       // Ahi 8K + Alo 8K + Bhi 4K + Blo 4K
#define CONV_SMEM (3*24576)      // 72 KB -> 3 CTAs/SM

// ---------------- device scratch ----------------
__device__ __align__(16) float g_v [PNUM*CNUM];
__device__ __align__(16) __nv_bfloat16 g_Vhi[NPOS*NTIL*CNUM];
__device__ __align__(16) __nv_bfloat16 g_Vlo[NPOS*NTIL*CNUM];
__device__ __align__(16) __nv_bfloat16 g_uhi1[NPOS*CNUM*CNUM];
__device__ __align__(16) __nv_bfloat16 g_ulo1[NPOS*CNUM*CNUM];
__device__ __align__(16) __nv_bfloat16 g_uhi2[NPOS*CNUM*CNUM];
__device__ __align__(16) __nv_bfloat16 g_ulo2[NPOS*CNUM*CNUM];
__device__ __align__(16) float g_m [NPOS*NTIL*CNUM];
__device__ __align__(16) float g_h [PNUM*CNUM];   // NORMALIZED h (post FC)
__device__ __align__(16) float g_xl[PNUM*CNUM];
__device__ float g_q2[PNUM];
__device__ float g_zn[512];
__device__ float g_pm [NTIL*CNUM];
__device__ float g_pm2[32*CNUM];
__device__ float g_pd[NTIL];
__device__ float g_pv[512];
__device__ float g_mu[CNUM];
__device__ float g_sc[8];
__device__ int   g_ctr  = 0;
__device__ int   g_ctr2 = 0;

// ---------------- PTX helpers ----------------
__device__ __forceinline__ uint32_t smem_u32(const void* p) {
    uint32_t a;
    asm("{ .reg .u64 t; cvta.to.shared.u64 t, %1; cvt.u32.u64 %0, t; }" : "=r"(a) : "l"(p));
    return a;
}
__device__ __forceinline__ void cpa16(uint32_t dst, const void* src) {
    asm volatile("cp.async.cg.shared.global [%0], [%1], 16;" :: "r"(dst), "l"(src) : "memory");
}
__device__ __forceinline__ void cp_commit() {
    asm volatile("cp.async.commit_group;" ::: "memory");
}
template<int N>
__device__ __forceinline__ void cp_wait() {
    asm volatile("cp.async.wait_group %0;" :: "n"(N) : "memory");
}
__device__ __forceinline__ void ldsm4(uint32_t* r, uint32_t addr) {
    asm volatile("ldmatrix.sync.aligned.m8n8.x4.shared.b16 {%0,%1,%2,%3}, [%4];"
        : "=r"(r[0]), "=r"(r[1]), "=r"(r[2]), "=r"(r[3]) : "r"(addr));
}
__device__ __forceinline__ void mma16816(float* d, const uint32_t* a, const uint32_t* b) {
    asm volatile("mma.sync.aligned.m16n8k16.row.col.f32.bf16.bf16.f32 "
        "{%0,%1,%2,%3}, {%4,%5,%6,%7}, {%8,%9}, {%0,%1,%2,%3};"
        : "+f"(d[0]), "+f"(d[1]), "+f"(d[2]), "+f"(d[3])
        : "r"(a[0]), "r"(a[1]), "r"(a[2]), "r"(a[3]), "r"(b[0]), "r"(b[1]));
}
__device__ __forceinline__ uint32_t swz(int r, int c) {
    return (uint32_t)(((r >> 1) << 7) | (((((r & 1) << 2) | c) ^ ((r >> 1) & 7)) << 4));
}

// fast atanh for |x| <= CLIP1 (two MUFU logs, no division)
__device__ __forceinline__ float atanh_fast(float x) {
    return 0.5f * (__logf(1.0f + x) - __logf(1.0f - x));
}

// ---------------- reductions ----------------
__device__ __forceinline__ float warpSum(float v) {
#pragma unroll
    for (int o = 16; o > 0; o >>= 1) v += __shfl_xor_sync(0xffffffffu, v, o);
    return v;
}
template<int K>
__device__ __forceinline__ void blockReduceK(float* v, float* sbuf) {
    int tid = threadIdx.x, lane = tid & 31, wid = tid >> 5;
#pragma unroll
    for (int i = 0; i < K; i++) {
        float x = v[i];
#pragma unroll
        for (int o = 16; o > 0; o >>= 1) x += __shfl_down_sync(0xffffffffu, x, o);
        if (lane == 0) sbuf[i*8 + wid] = x;
    }
    __syncthreads();
    if (tid == 0) {
#pragma unroll
        for (int i = 0; i < K; i++) {
            float s = sbuf[i*8];
            for (int w = 1; w < 8; w++) s += sbuf[i*8 + w];
            sbuf[i*8] = s;
        }
    }
    __syncthreads();
#pragma unroll
    for (int i = 0; i < K; i++) v[i] = sbuf[i*8];
    __syncthreads();
}

// ---------------- Winograd transforms ----------------
__device__ __forceinline__ void bt6(const float* in, float* out) {
    out[0] =  4.f*in[0] - 5.f*in[2] + in[4];
    out[1] = -4.f*in[1] - 4.f*in[2] + in[3] + in[4];
    out[2] =  4.f*in[1] - 4.f*in[2] - in[3] + in[4];
    out[3] = -2.f*in[1] -     in[2] + 2.f*in[3] + in[4];
    out[4] =  2.f*in[1] -     in[2] - 2.f*in[3] + in[4];
    out[5] =  4.f*in[1] - 5.f*in[3] + in[5];
}
__device__ __forceinline__ void g6(const float* in, float* out) {
    out[0] = 0.25f*in[0];
    out[1] = -(in[0] + in[1] + in[2]) * (1.f/6.f);
    out[2] = (-in[0] + in[1] - in[2]) * (1.f/6.f);
    out[3] = in[0]*(1.f/24.f) + in[1]*(1.f/12.f) + in[2]*(1.f/6.f);
    out[4] = in[0]*(1.f/24.f) - in[1]*(1.f/12.f) + in[2]*(1.f/6.f);
    out[5] = in[2];
}
__device__ __forceinline__ void at6(const float* in, float* out) {
    out[0] = in[0] + in[1] + in[2] + in[3] + in[4];
    out[1] = in[1] - in[2] + 2.f*(in[3] - in[4]);
    out[2] = in[1] + in[2] + 4.f*(in[3] + in[4]);
    out[3] = in[1] - in[2] + 8.f*(in[3] - in[4]) + in[5];
}

// ---------------- U = G z G^T (+ fused z column norms) ----------------
__global__ void wino_u(const float* __restrict__ z1, const float* __restrict__ z2) {
    __shared__ float sb[8];
    const float* z = blockIdx.y ? z2 : z1;
    __nv_bfloat16* uh = blockIdx.y ? g_uhi2 : g_uhi1;
    __nv_bfloat16* ul = blockIdx.y ? g_ulo2 : g_ulo1;
    int co = blockIdx.x, ci = threadIdx.x;
    float g[3][3];
    float nsum = 0.f;
#pragma unroll
    for (int i = 0; i < 3; i++)
#pragma unroll
        for (int j = 0; j < 3; j++) {
            float w = z[(size_t)((i*3 + j)*256 + ci)*256 + co];
            g[i][j] = w;
            nsum += w*w;
        }
    float r1[1] = { nsum };
    blockReduceK<1>(r1, sb);
    if (ci == 0) g_zn[blockIdx.y*256 + co] = sqrtf(fmaxf(r1[0], EPSF));

    float t[6][3];
#pragma unroll
    for (int j = 0; j < 3; j++) {
        float in[3] = { g[0][j], g[1][j], g[2][j] };
        float out[6];
        g6(in, out);
#pragma unroll
        for (int a = 0; a < 6; a++) t[a][j] = out[a];
    }
#pragma unroll
    for (int a = 0; a < 6; a++) {
        float out[6];
        g6(t[a], out);
#pragma unroll
        for (int b = 0; b < 6; b++) {
            float u = out[b];
            __nv_bfloat16 hi = __float2bfloat16(u);
            size_t idx = ((size_t)((a*6 + b)*256 + co))*256 + ci;
            uh[idx] = hi;
            ul[idx] = __float2bfloat16(u - __bfloat162float(hi));
        }
    }
}

// ---------------- V = B^T d B per tile ----------------
__global__ void wino_in() {
    int t = blockIdx.x, ci = threadIdx.x;
    int b = t >> 6, tr = (t >> 3) & 7, tc = t & 7;
    int base = b << 10;
    float d[6][6];
#pragma unroll
    for (int y = 0; y < 6; y++) {
        int iy = 4*tr - 1 + y;
#pragma unroll
        for (int x = 0; x < 6; x++) {
            int ix = 4*tc - 1 + x;
            bool ok = ((unsigned)iy < 32u) && ((unsigned)ix < 32u);
            d[y][x] = ok ? g_v[(size_t)(base + iy*32 + ix)*256 + ci] : 0.f;
        }
    }
    float e[6][6];
#pragma unroll
    for (int x = 0; x < 6; x++) {
        float in[6] = { d[0][x], d[1][x], d[2][x], d[3][x], d[4][x], d[5][x] };
        float out[6];
        bt6(in, out);
#pragma unroll
        for (int a = 0; a < 6; a++) e[a][x] = out[a];
    }
#pragma unroll
    for (int a = 0; a < 6; a++) {
        float out[6];
        bt6(e[a], out);
#pragma unroll
        for (int bb = 0; bb < 6; bb++) {
            float v = out[bb];
            __nv_bfloat16 hi = __float2bfloat16(v);
            size_t idx = ((size_t)((a*6 + bb)*NTIL + t))*256 + ci;
            g_Vhi[idx] = hi;
            g_Vlo[idx] = __float2bfloat16(v - __bfloat162float(hi));
        }
    }
}

// ---------------- batched Winograd GEMM (proven R11/R12 shape) ----------------
__global__ void __launch_bounds__(256, 3) wino_gemm(int which) {
    extern __shared__ __align__(16) char dsm[];
    uint32_t sbase = smem_u32(dsm);

    const __nv_bfloat16* Bh = which ? g_uhi2 : g_uhi1;
    const __nv_bfloat16* Bl = which ? g_ulo2 : g_ulo1;
    int t0  = blockIdx.x << 7;
    int nq  = blockIdx.y;
    int pos = blockIdx.z;

    int tid = threadIdx.x, wid = tid >> 5, l = tid & 31;

    int c4 = tid & 3;
    int r0 = tid >> 2;
    uint32_t ph0 = swz(r0, c4), ph1 = swz(r0 + 64, c4);
    const __nv_bfloat16* Abase_hi = g_Vhi + ((size_t)pos*NTIL + t0)*256;
    const __nv_bfloat16* Abase_lo = g_Vlo + ((size_t)pos*NTIL + t0)*256;
    const __nv_bfloat16* Bbase_hi = Bh + ((size_t)pos*256 + nq*64)*256;
    const __nv_bfloat16* Bbase_lo = Bl + ((size_t)pos*256 + nq*64)*256;
    size_t a0 = (size_t)r0*256 + c4*8, a1 = (size_t)(r0 + 64)*256 + c4*8;

    int m0 = (wid & 3) << 5;
    int n0w = (wid >> 2) << 5;
    int mi = l >> 3;
    int rA = m0 + ((mi & 1) << 3) + (l & 7);
    uint32_t qA0 = swz(rA, mi >> 1);
    int rB = n0w + (((mi >> 1) & 1) << 3) + (l & 7);
    uint32_t qB0 = swz(rB, mi & 1);

    float acc[2][4][4];
#pragma unroll
    for (int i = 0; i < 2; i++)
#pragma unroll
        for (int j = 0; j < 4; j++)
#pragma unroll
            for (int k = 0; k < 4; k++) acc[i][j][k] = 0.f;

    auto load_chunk = [&](int kc, int stage) {
        size_t coff = (size_t)(kc << 5);
        uint32_t st = sbase + (uint32_t)stage*STAGE_BYTES;
        cpa16(st + ph0,         Abase_hi + a0 + coff);
        cpa16(st + 8192 + ph0,  Abase_lo + a0 + coff);
        cpa16(st + ph1,         Abase_hi + a1 + coff);
        cpa16(st + 8192 + ph1,  Abase_lo + a1 + coff);
        cpa16(st + 16384 + ph0, Bbase_hi + a0 + coff);
        cpa16(st + 20480 + ph0, Bbase_lo + a0 + coff);
        cp_commit();
    };

    load_chunk(0, 0);
    load_chunk(1, 1);

    for (int kc = 0; kc < 8; kc++) {
        int stage = kc % 3;
        if (kc < 6) cp_wait<1>(); else cp_wait<0>();
        __syncthreads();
        if (kc + 2 < 8) load_chunk(kc + 2, (kc + 2) % 3);

        uint32_t st = sbase + (uint32_t)stage*STAGE_BYTES;
        uint32_t Ahi = st, Alo = st + 8192, Bhi = st + 16384, Blo = st + 20480;
#pragma unroll
        for (int ks = 0; ks < 2; ks++) {
            uint32_t kx = (uint32_t)(ks << 5);
            uint32_t qa = qA0 ^ kx, qb = qB0 ^ kx;
            uint32_t ah[8], al[8], bbv[8];
            ldsm4(bbv,     Bhi + qb);
            ldsm4(bbv + 4, Bhi + qb + 1024);
            ldsm4(ah,     Ahi + qa);
            ldsm4(ah + 4, Ahi + qa + 1024);
            ldsm4(al,     Alo + qa);
            ldsm4(al + 4, Alo + qa + 1024);
#pragma unroll
            for (int nf = 0; nf < 4; nf++) {
                const uint32_t* bp = bbv + nf*2;
                mma16816(acc[0][nf], ah,     bp);
                mma16816(acc[1][nf], ah + 4, bp);
            }
#pragma unroll
            for (int nf = 0; nf < 4; nf++) {
                const uint32_t* bp = bbv + nf*2;
                mma16816(acc[0][nf], al,     bp);
                mma16816(acc[1][nf], al + 4, bp);
            }
            ldsm4(bbv,     Blo + qb);
            ldsm4(bbv + 4, Blo + qb + 1024);
#pragma unroll
            for (int nf = 0; nf < 4; nf++) {
                const uint32_t* bp = bbv + nf*2;
                mma16816(acc[0][nf], ah,     bp);
                mma16816(acc[1][nf], ah + 4, bp);
            }
        }
    }

    int row0 = m0 + (l >> 2);
    int col0 = n0w + ((l & 3) << 1);
    float* gm = g_m + ((size_t)pos*NTIL + t0)*256 + nq*64;
#pragma unroll
    for (int mf = 0; mf < 2; mf++)
#pragma unroll
        for (int hf = 0; hf < 2; hf++) {
            int r = row0 + mf*16 + hf*8;
            float* rowp = gm + (size_t)r*256;
#pragma unroll
            for (int nf = 0; nf < 4; nf++)
                *(float2*)(rowp + col0 + nf*8) =
                    make_float2(acc[mf][nf][hf*2], acc[mf][nf][hf*2 + 1]);
        }
}

// ---------------- pre2 (+ fused xT) ----------------
__global__ void pre2_kernel(const float* __restrict__ x, float scale) {
    __shared__ float sx[256][33];
    int tid = threadIdx.x, lane = tid & 31, w8 = tid >> 5;
    int p0 = blockIdx.x * 32;
    int b = p0 >> 10, hw0 = p0 & 1023;
#pragma unroll 8
    for (int i = 0; i < 32; i++) {
        int c = i*8 + w8;
        sx[c][lane] = x[(size_t)(b*256 + c)*1024 + hw0 + lane];
    }
    __syncthreads();
#pragma unroll 8
    for (int pl = 0; pl < 32; pl++)
        g_xl[(size_t)(p0 + pl)*256 + tid] = sx[tid][pl];
#pragma unroll
    for (int pp = 0; pp < 4; pp++) {
        int pl = w8*4 + pp;
        int p = p0 + pl;
        float xv[8];
#pragma unroll
        for (int i = 0; i < 8; i++) xv[i] = sx[lane*8 + i][pl];
        float q = 0.f;
#pragma unroll
        for (int i = 0; i < 8; i++) q += xv[i]*xv[i];
        float n2 = warpSum(q);
        float n = sqrtf(fmaxf(n2, EPSF));
        float f = atanh_fast(fminf(n, CLIP1)) / n * scale;
        float4 o0 = make_float4(f*xv[0], f*xv[1], f*xv[2], f*xv[3]);
        float4 o1 = make_float4(f*xv[4], f*xv[5], f*xv[6], f*xv[7]);
        float* dst = g_v + (size_t)p*256 + lane*8;
        *(float4*)dst = o0;
        *(float4*)(dst + 4) = o1;
        if (lane == 0) g_q2[p] = f*f*n2;
    }
}

// ---------------- per-pixel s ----------------
__device__ __forceinline__ float s_from_q2(int p) {
    int h = (p >> 5) & 31, w = p & 31;
    float np2 = 0.f;
#pragma unroll
    for (int dy = -1; dy <= 1; dy++)
#pragma unroll
        for (int dx = -1; dx <= 1; dx++) {
            int sh = h + dy, sw = w + dx;
            if ((unsigned)sh < 32u && (unsigned)sw < 32u) np2 += g_q2[p + dy*32 + dx];
        }
    float np = sqrtf(fmaxf(np2, EPSF));
    float th = tanhf(np);
    float uf = th / np;
    float un = th;
    if (un > MAXN) { uf *= MAXN/un; un = MAXN; }
    float lam = 2.0f / fmaxf(1.0f - un*un, EPSF);
    return lam * uf;
}

// ---------------- output transform + FC + BN partials; writes NORMALIZED h ----------------
__global__ void wino_out(int znoff) {
    __shared__ float ss[16];
    __shared__ float slam[16];
    __shared__ float sld[16];
    __shared__ float sinv[16];
    __shared__ float ybuf[16][260];
    int t = blockIdx.x, co = threadIdx.x;
    int b = t >> 6, tr = (t >> 3) & 7, tc = t & 7;
    int prow = (b << 10) + (4*tr)*32 + 4*tc;
    if (co < 16) {
        int r = co >> 2, c = co & 3;
        ss[co] = s_from_q2(prow + r*32 + c);
    }
    float m[36];
#pragma unroll
    for (int pos = 0; pos < 36; pos++)
        m[pos] = g_m[((size_t)pos*NTIL + t)*256 + co];
    float Z[4][6];
#pragma unroll
    for (int bb = 0; bb < 6; bb++) {
        float in[6] = { m[bb], m[6+bb], m[12+bb], m[18+bb], m[24+bb], m[30+bb] };
        float out[4];
        at6(in, out);
#pragma unroll
        for (int r = 0; r < 4; r++) Z[r][bb] = out[r];
    }
    float zn = g_zn[znoff + co];
    float izn = 1.0f / zn;
    float a2 = 2.0f * zn;
    __syncthreads();
#pragma unroll
    for (int r = 0; r < 4; r++) {
        float Y[4];
        at6(Z[r], Y);
#pragma unroll
        for (int c = 0; c < 4; c++) {
            float s = ss[r*4 + c];
            float tt = Y[c] * s * izn;
            float w = tt + sqrtf(fmaf(tt, tt, 1.0f));
            float u = __logf(w);
            float au = a2 * u;
            ybuf[r*4 + c][co] = 0.5f * (__expf(au) - __expf(-au));
        }
    }
    __syncthreads();
    int wd = co >> 5, lid = co & 31;
#pragma unroll
    for (int k = 0; k < 2; k++) {
        int pl = wd*2 + k;
        float q = 0.f;
#pragma unroll
        for (int i = 0; i < 8; i++) {
            float v = ybuf[pl][lid*8 + i];
            q += v*v;
        }
        float tot = warpSum(q);
        float inv = 1.0f / (1.0f + sqrtf(1.0f + tot));
        float n2 = tot*inv*inv;
        float lam = 2.0f / fmaxf(1.0f - n2, EPSF);
        if (lid == 0) { slam[pl] = lam*inv; sld[pl] = lam - 1.0f; sinv[pl] = inv; }
    }
    __syncthreads();
    float accm = 0.f;
#pragma unroll
    for (int pl = 0; pl < 16; pl++)
        accm += slam[pl] * ybuf[pl][co];
    g_pm[t*256 + co] = accm;
    if (co == 0) {
        float d = 0.f;
#pragma unroll
        for (int pl = 0; pl < 16; pl++) d += sld[pl];
        g_pd[t] = d;
    }
#pragma unroll
    for (int pl = 0; pl < 16; pl++) {
        int p = prow + (pl >> 2)*32 + (pl & 3);
        g_h[(size_t)p*256 + co] = ybuf[pl][co] * sinv[pl];
    }
}

// ---------------- BN mu: 32-block partial sum + last-block finalize ----------------
__global__ void bnmu_kernel(const float* __restrict__ bias) {
    __shared__ float sb[24];
    __shared__ int slast;
    int c = threadIdx.x;
    float s = 0.f;
    int g0 = blockIdx.x * 32;
    for (int g = 0; g < 32; g++) s += g_pm[(g0 + g)*256 + c];
    g_pm2[blockIdx.x*256 + c] = s;
    __threadfence();
    if (c == 0) slast = (atomicAdd(&g_ctr2, 1) == 31);
    __syncthreads();
    if (!slast) return;
    __threadfence();
    float msum = 0.f;
#pragma unroll
    for (int j = 0; j < 32; j++) msum += g_pm2[j*256 + c];
    float dv = 0.f;
#pragma unroll
    for (int j = 0; j < 4; j++) dv += g_pd[j*256 + c];
    float r1[1] = { dv };
    blockReduceK<1>(r1, sb);
    float den = fmaxf(r1[0], EPSF);
    float m = msum / den;
    float r2[1] = { m*m };
    blockReduceK<1>(r2, sb);
    float nm = sqrtf(fmaxf(r2[0], EPSF));
    float fac = tanhf(0.5f * atanh_fast(fminf(nm, CLIP1))) / nm;
    float muc = fac * m;
    g_mu[c] = muc;
    float bc = bias[c];
    float r3[3] = { muc*muc, bc*bc, bc*muc };
    blockReduceK<3>(r3, sb);
    if (c == 0) {
        float mu2 = r3[0], b2 = r3[1], bm = r3[2];
        g_sc[0] = mu2;
        g_sc[1] = 2.0f / fmaxf(1.0f - mu2, EPSF);
        g_sc[2] = b2;
        g_sc[3] = 2.0f / fmaxf(1.0f - b2, EPSF);
        g_sc[4] = bm;
        ((volatile float*)g_sc)[5] = 0.f;
        g_ctr2 = 0;
    }
}

// ---------------- variance partial (normalized input) ----------------
__device__ __forceinline__ float var_pixel(int p, const float* mu8, float mu2) {
    int lid = threadIdx.x & 31;
    const float4* row = (const float4*)(g_h + (size_t)p*256 + lid*8);
    float4 a = row[0], cc = row[1];
    float v[8] = {a.x,a.y,a.z,a.w,cc.x,cc.y,cc.z,cc.w};
    float q1 = 0.f, q2 = 0.f;
#pragma unroll
    for (int j = 0; j < 8; j++) { q1 += v[j]*v[j]; q2 += v[j]*mu8[j]; }
    float xp2 = warpSum(q1);
    float ip  = warpSum(q2);
    float A = 1.0f - 2.0f*ip + mu2;
    float B = 1.0f - xp2;
    float nn = fmaxf(A*A*xp2 - 2.0f*A*B*ip + B*B*mu2, 0.f);
    float den = fmaxf(1.0f - 2.0f*ip + xp2*mu2, EPSF);
    float nr = sqrtf(fmaxf(nn/(den*den), EPSF));
    float dd = 2.0f * atanh_fast(fminf(nr, CLIP1));
    return dd*dd;
}

// ---------------- shared BN point transform ----------------
__device__ __forceinline__ float bn_point_w(const float* xv, const float* mu8, const float* b8,
                                            float* hc) {
    float mu2 = g_sc[0], lam_mu = g_sc[1], b2 = g_sc[2], lam_b = g_sc[3],
          bm = g_sc[4], rstd = g_sc[5];
    float s0 = 0.f, s1 = 0.f, s2 = 0.f;
#pragma unroll
    for (int i = 0; i < 8; i++) { s0 += xv[i]*xv[i]; s1 += mu8[i]*xv[i]; s2 += b8[i]*xv[i]; }
    float xp2 = warpSum(s0), ip = warpSum(s1), bx = warpSum(s2);
    float A  = 1.0f - 2.0f*ip + xp2;
    float Bc = 1.0f - mu2;
    float den = fmaxf(1.0f - 2.0f*ip + mu2*xp2, EPSF);
    float nd2 = fmaxf(A*A*mu2 - 2.0f*A*Bc*ip + Bc*Bc*xp2, 0.f) / (den*den);
    float nd = sqrtf(fmaxf(nd2, EPSF));
    float cv = (2.0f/lam_mu) * atanh_fast(fminf(nd, CLIP1)) / nd;
    float uw = cv * (Bc*bx - A*bm) / den;
    float vw = cv * (A*mu2 - Bc*ip) / den;
    float av  = -uw*mu2 - vw - 2.0f*bm*vw;
    float bv2 = -vw*b2 + uw;
    float dgy = fmaxf(1.0f - 2.0f*bm + b2*mu2, EPSF);
    float fac = (lam_mu / lam_b) * rstd;
    float uc[8];
    float t0 = 0.f, t1 = 0.f;
#pragma unroll
    for (int i = 0; i < 8; i++) {
        float vc = cv * (Bc*xv[i] - A*mu8[i]) / den;
        uc[i] = (vc + 2.0f*(av*b8[i] - bv2*mu8[i]) / dgy) * fac;
        t0 += uc[i]*uc[i];
        t1 += b8[i]*uc[i];
    }
    float u2 = warpSum(t0), bu = warpSum(t1);
    float nu = sqrtf(fmaxf(u2, EPSF));
    float tf = tanhf(0.5f * lam_b * nu) / nu;
    float s2m = tf*tf*u2;
    float bs  = tf*bu;
    float A3 = 1.0f + 2.0f*bs + s2m, B3 = 1.0f - b2;
    float den3 = fmaxf(1.0f + 2.0f*bs + b2*s2m, EPSF);
#pragma unroll
    for (int i = 0; i < 8; i++) hc[i] = (A3*b8[i] + B3*tf*uc[i]) / den3;
    float nh2 = fmaxf(A3*A3*b2 + 2.0f*A3*B3*bs + B3*B3*s2m, 0.f) / (den3*den3);
    float nh = sqrtf(fmaxf(nh2, EPSF));
    if (nh > MAXN) {
        float q = MAXN / nh;
#pragma unroll
        for (int i = 0; i < 8; i++) hc[i] *= q;
        nh = MAXN;
    }
    return nh;
}

// ---------------- FUSED variance + BN apply + hrelu + pre-for-conv2 ----------------
__global__ void bnva_kernel(const float* __restrict__ bias, const float* __restrict__ weight,
                            float scale) {
    __shared__ float sv[8];
    __shared__ int slast;
    int wid = threadIdx.x >> 5, lid = threadIdx.x & 31;
    int p0 = blockIdx.x * 64;
    float mu8[8];
#pragma unroll
    for (int j = 0; j < 8; j++) mu8[j] = g_mu[lid*8 + j];
    float mu2 = g_sc[0];
    float acc = 0.f;
    for (int i = 0; i < 8; i++)
        acc += var_pixel(p0 + wid*8 + i, mu8, mu2);
    if (lid == 0) sv[wid] = acc;
    __syncthreads();
    if (threadIdx.x == 0) {
        float s = 0.f;
        for (int w = 0; w < 8; w++) s += sv[w];
        g_pv[blockIdx.x] = s;
        __threadfence();
        slast = (atomicAdd(&g_ctr, 1) == 255);
    }
    __syncthreads();
    if (slast) {
        float v = g_pv[threadIdx.x];
        __shared__ float sb[8];
        float r[1] = { v };
        blockReduceK<1>(r, sb);
        if (threadIdx.x == 0) {
            float var = r[0] / 16384.0f;
            g_ctr = 0;
            __threadfence();
            ((volatile float*)g_sc)[5] = sqrtf(weight[0] / fmaxf(var, EPSF));
        }
    }
    if (threadIdx.x == 0) {
        volatile float* vs = g_sc;
        while (vs[5] == 0.f) { }
    }
    __syncthreads();
    float b8[8];
#pragma unroll
    for (int j = 0; j < 8; j++) b8[j] = bias[lid*8 + j];
    for (int i = 0; i < 8; i++) {
        int p = p0 + wid*8 + i;
        const float4* row = (const float4*)(g_h + (size_t)p*256 + lid*8);
        float4 a = row[0], cc = row[1];
        float xv[8] = {a.x,a.y,a.z,a.w,cc.x,cc.y,cc.z,cc.w};
        float hc[8];
        float nh = bn_point_w(xv, mu8, b8, hc);
        float lf = atanh_fast(fminf(nh, CLIP1)) / nh;
        float rc[8];
        float q = 0.f;
#pragma unroll
        for (int k = 0; k < 8; k++) { rc[k] = fmaxf(lf*hc[k], 0.f); q += rc[k]*rc[k]; }
        float rs = warpSum(q);
        float nr = sqrtf(fmaxf(rs, EPSF));
        float ef = tanhf(nr) / nr;
        float nhr = sqrtf(fmaxf(ef*ef*rs, EPSF));
        float adj = 1.0f;
        if (nhr > MAXN) { adj = MAXN/nhr; nhr = MAXN; }
        float f3 = atanh_fast(fminf(nhr, CLIP1)) / nhr * scale;
        float g = f3 * ef * adj;
        float4 o0 = make_float4(g*rc[0], g*rc[1], g*rc[2], g*rc[3]);
        float4 o1 = make_float4(g*rc[4], g*rc[5], g*rc[6], g*rc[7]);
        float* dst = g_v + (size_t)p*256 + lid*8;
        *(float4*)dst = o0;
        *(float4*)(dst + 4) = o1;
        if (lid == 0) g_q2[p] = f3*f3*nhr*nhr;
    }
}

// ---------------- FUSED variance + BN2 apply + residual + hrelu + NCHW out ----------------
__global__ void bnvf_kernel(const float* __restrict__ bias, const float* __restrict__ weight,
                            float* __restrict__ out) {
    __shared__ float so[256][33];
    __shared__ float sv[8];
    __shared__ int slast;
    int tid = threadIdx.x, lane = tid & 31, w8 = tid >> 5;
    int p0 = blockIdx.x * 32;
    int b = p0 >> 10, hw0 = p0 & 1023;
    float mu8[8], b8[8];
#pragma unroll
    for (int j = 0; j < 8; j++) { mu8[j] = g_mu[lane*8 + j]; b8[j] = bias[lane*8 + j]; }
    float mu2 = g_sc[0];
    float acc = 0.f;
    for (int i = 0; i < 4; i++)
        acc += var_pixel(p0 + w8*4 + i, mu8, mu2);
    if (lane == 0) sv[w8] = acc;
    __syncthreads();
    if (tid == 0) {
        float s = 0.f;
        for (int w = 0; w < 8; w++) s += sv[w];
        g_pv[blockIdx.x] = s;
        __threadfence();
        slast = (atomicAdd(&g_ctr, 1) == 511);
    }
    __syncthreads();
    if (slast) {
        float v = g_pv[tid] + g_pv[tid + 256];
        __shared__ float sb[8];
        float r[1] = { v };
        blockReduceK<1>(r, sb);
        if (tid == 0) {
            float var = r[0] / 16384.0f;
            g_ctr = 0;
            __threadfence();
            ((volatile float*)g_sc)[5] = sqrtf(weight[0] / fmaxf(var, EPSF));
        }
    }
    if (tid == 0) {
        volatile float* vs = g_sc;
        while (vs[5] == 0.f) { }
    }
    __syncthreads();
#pragma unroll
    for (int pp = 0; pp < 4; pp++) {
        int pl = w8*4 + pp;
        int p = p0 + pl;
        const float4* row = (const float4*)(g_h + (size_t)p*256 + lane*8);
        float4 a = row[0], cc = row[1];
        float xv[8] = {a.x,a.y,a.z,a.w,cc.x,cc.y,cc.z,cc.w};
        float hc[8];
        float nh = bn_point_w(xv, mu8, b8, hc);
        const float4* rrow = (const float4*)(g_xl + (size_t)p*256 + lane*8);
        float4 r0 = rrow[0], r1 = rrow[1];
        float res[8] = {r0.x,r0.y,r0.z,r0.w,r1.x,r1.y,r1.z,r1.w};
        float q1 = 0.f, q2 = 0.f;
#pragma unroll
        for (int i = 0; i < 8; i++) { q1 += res[i]*res[i]; q2 += hc[i]*res[i]; }
        float y2 = warpSum(q1), xy = warpSum(q2);
        float x2 = nh*nh;
        float A4 = 1.0f + 2.0f*xy + y2, B4 = 1.0f - x2;
        float den4 = fmaxf(1.0f + 2.0f*xy + x2*y2, EPSF);
        float hm[8];
#pragma unroll
        for (int i = 0; i < 8; i++) hm[i] = (A4*hc[i] + B4*res[i]) / den4;
        float nm2 = fmaxf(A4*A4*x2 + 2.0f*A4*B4*xy + B4*B4*y2, 0.f) / (den4*den4);
        float nmv = sqrtf(fmaxf(nm2, EPSF));
        float lf = atanh_fast(fminf(nmv, CLIP1)) / nmv;
        float rc[8];
        float q = 0.f;
#pragma unroll
        for (int i = 0; i < 8; i++) { rc[i] = fmaxf(lf*hm[i], 0.f); q += rc[i]*rc[i]; }
        float rs = warpSum(q);
        float nr = sqrtf(fmaxf(rs, EPSF));
        float ef = tanhf(nr) / nr;
        float nhr = sqrtf(fmaxf(ef*ef*rs, EPSF));
        float adj = (nhr > MAXN) ? MAXN/nhr : 1.0f;
#pragma unroll
        for (int i = 0; i < 8; i++) so[lane*8 + i][pl] = ef * adj * rc[i];
    }
    __syncthreads();
#pragma unroll 8
    for (int i = 0; i < 32; i++) {
        int c = i*8 + w8;
        out[(size_t)(b*256 + c)*1024 + hw0 + lane] = so[c][lane];
    }
}

// ---------------- launcher ----------------
extern "C" void kernel_launch(void* const* d_in, const int* in_sizes, int n_in,
                              void* d_out, int out_size) {
    const float* x  = (const float*)d_in[0];
    const float* z1 = (const float*)d_in[1];
    const float* z2 = (const float*)d_in[2];
    const float* w1 = (const float*)d_in[3];
    const float* b1 = (const float*)d_in[4];
    const float* w2 = (const float*)d_in[5];
    const float* b2 = (const float*)d_in[6];
    float* out = (float*)d_out;

    // scale = Beta(1152, 0.5) / Beta(128, 0.5)
    double lg = lgamma(1152.0) - lgamma(1152.5) - lgamma(128.0) + lgamma(128.5);
    float scale = (float)exp(lg);

    static int smem_set = 0;
    if (!smem_set) {
        cudaFuncSetAttribute(wino_gemm, cudaFuncAttributeMaxDynamicSharedMemorySize, CONV_SMEM);
        smem_set = 1;
    }

    dim3 ggrid(8, 4, 36);

    wino_u<<<dim3(256, 2), 256>>>(z1, z2);       // 0
    pre2_kernel<<<PNUM/32, 256>>>(x, scale);     // 1
    wino_in<<<NTIL, 256>>>();                    // 2
    wino_gemm<<<ggrid, 256, CONV_SMEM>>>(0);     // 3  <- ncu capture target
    wino_out<<<NTIL, 256>>>(0);

    bnmu_kernel<<<32, 256>>>(b1);
    bnva_kernel<<<256, 256>>>(b1, w1, scale);

    wino_in<<<NTIL, 256>>>();
    wino_gemm<<<ggrid, 256, CONV_SMEM>>>(1);
    wino_out<<<NTIL, 256>>>(256);

    bnmu_kernel<<<32, 256>>>(b2);
    bnvf_kernel<<<512, 256>>>(b2, w2, out);
}

// round 17
// speedup vs baseline: 1.2049x; 1.0800x over previous
#include <cuda_runtime.h>
#include <cuda_bf16.h>
#include <math.h>
#include <stdint.h>

// Problem constants: B=16, C=256, H=W=32
#define PNUM 16384
#define CNUM 256
#define CLIP1 0.9999999f
#define MAXN  0.99999f
#define EPSF  1e-15f

#define NPOS 36
#define NTIL 1024
#define STAGE_BYTES 24576u       // Ahi 8K + Alo 8K + Bhi 4K + Blo 4K
#define CONV_SMEM (3*24576)      // 72 KB -> 3 CTAs/SM

// ---------------- device scratch ----------------
__device__ __align__(16) float g_v [PNUM*CNUM];
__device__ __align__(16) __nv_bfloat16 g_Vhi[NPOS*NTIL*CNUM];
__device__ __align__(16) __nv_bfloat16 g_Vlo[NPOS*NTIL*CNUM];
__device__ __align__(16) __nv_bfloat16 g_uhi1[NPOS*CNUM*CNUM];
__device__ __align__(16) __nv_bfloat16 g_ulo1[NPOS*CNUM*CNUM];
__device__ __align__(16) __nv_bfloat16 g_uhi2[NPOS*CNUM*CNUM];
__device__ __align__(16) __nv_bfloat16 g_ulo2[NPOS*CNUM*CNUM];
__device__ __align__(16) float g_m [NPOS*NTIL*CNUM];
__device__ __align__(16) float g_h [PNUM*CNUM];   // NORMALIZED h (post FC)
__device__ __align__(16) float g_xl[PNUM*CNUM];
__device__ float g_q2[PNUM];
__device__ float g_zn[512];
__device__ float g_pm [NTIL*CNUM];
__device__ float g_pm2[32*CNUM];
__device__ float g_pd[NTIL];
__device__ float g_pv[512];
__device__ float g_mu[CNUM];
__device__ float g_sc[8];
__device__ int   g_ctr  = 0;
__device__ int   g_ctr2 = 0;

// ---------------- PTX helpers ----------------
__device__ __forceinline__ uint32_t smem_u32(const void* p) {
    uint32_t a;
    asm("{ .reg .u64 t; cvta.to.shared.u64 t, %1; cvt.u32.u64 %0, t; }" : "=r"(a) : "l"(p));
    return a;
}
__device__ __forceinline__ void cpa16(uint32_t dst, const void* src) {
    asm volatile("cp.async.cg.shared.global [%0], [%1], 16;" :: "r"(dst), "l"(src) : "memory");
}
__device__ __forceinline__ void cp_commit() {
    asm volatile("cp.async.commit_group;" ::: "memory");
}
template<int N>
__device__ __forceinline__ void cp_wait() {
    asm volatile("cp.async.wait_group %0;" :: "n"(N) : "memory");
}
__device__ __forceinline__ void ldsm4(uint32_t* r, uint32_t addr) {
    asm volatile("ldmatrix.sync.aligned.m8n8.x4.shared.b16 {%0,%1,%2,%3}, [%4];"
        : "=r"(r[0]), "=r"(r[1]), "=r"(r[2]), "=r"(r[3]) : "r"(addr));
}
__device__ __forceinline__ void mma16816(float* d, const uint32_t* a, const uint32_t* b) {
    asm volatile("mma.sync.aligned.m16n8k16.row.col.f32.bf16.bf16.f32 "
        "{%0,%1,%2,%3}, {%4,%5,%6,%7}, {%8,%9}, {%0,%1,%2,%3};"
        : "+f"(d[0]), "+f"(d[1]), "+f"(d[2]), "+f"(d[3])
        : "r"(a[0]), "r"(a[1]), "r"(a[2]), "r"(a[3]), "r"(b[0]), "r"(b[1]));
}
__device__ __forceinline__ uint32_t swz(int r, int c) {
    return (uint32_t)(((r >> 1) << 7) | (((((r & 1) << 2) | c) ^ ((r >> 1) & 7)) << 4));
}

// ---------------- fast math (per-pixel paths only; gemm untouched) ----------------
__device__ __forceinline__ float fdivf(float a, float b) { return __fdividef(a, b); }
// fast atanh for |x| <= CLIP1
__device__ __forceinline__ float atanh_fast(float x) {
    return 0.5f * (__logf(1.0f + x) - __logf(1.0f - x));
}
// fast tanh for x >= 0 (norms); saturates correctly to 1
__device__ __forceinline__ float tanh_fast(float x) {
    float e = __expf(2.0f * x);
    return 1.0f - __fdividef(2.0f, e + 1.0f);
}

// ---------------- reductions ----------------
__device__ __forceinline__ float warpSum(float v) {
#pragma unroll
    for (int o = 16; o > 0; o >>= 1) v += __shfl_xor_sync(0xffffffffu, v, o);
    return v;
}
template<int K>
__device__ __forceinline__ void blockReduceK(float* v, float* sbuf) {
    int tid = threadIdx.x, lane = tid & 31, wid = tid >> 5;
#pragma unroll
    for (int i = 0; i < K; i++) {
        float x = v[i];
#pragma unroll
        for (int o = 16; o > 0; o >>= 1) x += __shfl_down_sync(0xffffffffu, x, o);
        if (lane == 0) sbuf[i*8 + wid] = x;
    }
    __syncthreads();
    if (tid == 0) {
#pragma unroll
        for (int i = 0; i < K; i++) {
            float s = sbuf[i*8];
            for (int w = 1; w < 8; w++) s += sbuf[i*8 + w];
            sbuf[i*8] = s;
        }
    }
    __syncthreads();
#pragma unroll
    for (int i = 0; i < K; i++) v[i] = sbuf[i*8];
    __syncthreads();
}

// ---------------- Winograd transforms ----------------
__device__ __forceinline__ void bt6(const float* in, float* out) {
    out[0] =  4.f*in[0] - 5.f*in[2] + in[4];
    out[1] = -4.f*in[1] - 4.f*in[2] + in[3] + in[4];
    out[2] =  4.f*in[1] - 4.f*in[2] - in[3] + in[4];
    out[3] = -2.f*in[1] -     in[2] + 2.f*in[3] + in[4];
    out[4] =  2.f*in[1] -     in[2] - 2.f*in[3] + in[4];
    out[5] =  4.f*in[1] - 5.f*in[3] + in[5];
}
__device__ __forceinline__ void g6(const float* in, float* out) {
    out[0] = 0.25f*in[0];
    out[1] = -(in[0] + in[1] + in[2]) * (1.f/6.f);
    out[2] = (-in[0] + in[1] - in[2]) * (1.f/6.f);
    out[3] = in[0]*(1.f/24.f) + in[1]*(1.f/12.f) + in[2]*(1.f/6.f);
    out[4] = in[0]*(1.f/24.f) - in[1]*(1.f/12.f) + in[2]*(1.f/6.f);
    out[5] = in[2];
}
__device__ __forceinline__ void at6(const float* in, float* out) {
    out[0] = in[0] + in[1] + in[2] + in[3] + in[4];
    out[1] = in[1] - in[2] + 2.f*(in[3] - in[4]);
    out[2] = in[1] + in[2] + 4.f*(in[3] + in[4]);
    out[3] = in[1] - in[2] + 8.f*(in[3] - in[4]) + in[5];
}

// ---------------- U = G z G^T (+ fused z column norms) ----------------
__global__ void wino_u(const float* __restrict__ z1, const float* __restrict__ z2) {
    __shared__ float sb[8];
    const float* z = blockIdx.y ? z2 : z1;
    __nv_bfloat16* uh = blockIdx.y ? g_uhi2 : g_uhi1;
    __nv_bfloat16* ul = blockIdx.y ? g_ulo2 : g_ulo1;
    int co = blockIdx.x, ci = threadIdx.x;
    float g[3][3];
    float nsum = 0.f;
#pragma unroll
    for (int i = 0; i < 3; i++)
#pragma unroll
        for (int j = 0; j < 3; j++) {
            float w = z[(size_t)((i*3 + j)*256 + ci)*256 + co];
            g[i][j] = w;
            nsum += w*w;
        }
    float r1[1] = { nsum };
    blockReduceK<1>(r1, sb);
    if (ci == 0) g_zn[blockIdx.y*256 + co] = sqrtf(fmaxf(r1[0], EPSF));

    float t[6][3];
#pragma unroll
    for (int j = 0; j < 3; j++) {
        float in[3] = { g[0][j], g[1][j], g[2][j] };
        float out[6];
        g6(in, out);
#pragma unroll
        for (int a = 0; a < 6; a++) t[a][j] = out[a];
    }
#pragma unroll
    for (int a = 0; a < 6; a++) {
        float out[6];
        g6(t[a], out);
#pragma unroll
        for (int b = 0; b < 6; b++) {
            float u = out[b];
            __nv_bfloat16 hi = __float2bfloat16(u);
            size_t idx = ((size_t)((a*6 + b)*256 + co))*256 + ci;
            uh[idx] = hi;
            ul[idx] = __float2bfloat16(u - __bfloat162float(hi));
        }
    }
}

// ---------------- V = B^T d B per tile ----------------
__global__ void wino_in() {
    int t = blockIdx.x, ci = threadIdx.x;
    int b = t >> 6, tr = (t >> 3) & 7, tc = t & 7;
    int base = b << 10;
    float d[6][6];
#pragma unroll
    for (int y = 0; y < 6; y++) {
        int iy = 4*tr - 1 + y;
#pragma unroll
        for (int x = 0; x < 6; x++) {
            int ix = 4*tc - 1 + x;
            bool ok = ((unsigned)iy < 32u) && ((unsigned)ix < 32u);
            d[y][x] = ok ? g_v[(size_t)(base + iy*32 + ix)*256 + ci] : 0.f;
        }
    }
    float e[6][6];
#pragma unroll
    for (int x = 0; x < 6; x++) {
        float in[6] = { d[0][x], d[1][x], d[2][x], d[3][x], d[4][x], d[5][x] };
        float out[6];
        bt6(in, out);
#pragma unroll
        for (int a = 0; a < 6; a++) e[a][x] = out[a];
    }
#pragma unroll
    for (int a = 0; a < 6; a++) {
        float out[6];
        bt6(e[a], out);
#pragma unroll
        for (int bb = 0; bb < 6; bb++) {
            float v = out[bb];
            __nv_bfloat16 hi = __float2bfloat16(v);
            size_t idx = ((size_t)((a*6 + bb)*NTIL + t))*256 + ci;
            g_Vhi[idx] = hi;
            g_Vlo[idx] = __float2bfloat16(v - __bfloat162float(hi));
        }
    }
}

// ---------------- batched Winograd GEMM (proven shape; UNCHANGED) ----------------
__global__ void __launch_bounds__(256, 3) wino_gemm(int which) {
    extern __shared__ __align__(16) char dsm[];
    uint32_t sbase = smem_u32(dsm);

    const __nv_bfloat16* Bh = which ? g_uhi2 : g_uhi1;
    const __nv_bfloat16* Bl = which ? g_ulo2 : g_ulo1;
    int t0  = blockIdx.x << 7;
    int nq  = blockIdx.y;
    int pos = blockIdx.z;

    int tid = threadIdx.x, wid = tid >> 5, l = tid & 31;

    int c4 = tid & 3;
    int r0 = tid >> 2;
    uint32_t ph0 = swz(r0, c4), ph1 = swz(r0 + 64, c4);
    const __nv_bfloat16* Abase_hi = g_Vhi + ((size_t)pos*NTIL + t0)*256;
    const __nv_bfloat16* Abase_lo = g_Vlo + ((size_t)pos*NTIL + t0)*256;
    const __nv_bfloat16* Bbase_hi = Bh + ((size_t)pos*256 + nq*64)*256;
    const __nv_bfloat16* Bbase_lo = Bl + ((size_t)pos*256 + nq*64)*256;
    size_t a0 = (size_t)r0*256 + c4*8, a1 = (size_t)(r0 + 64)*256 + c4*8;

    int m0 = (wid & 3) << 5;
    int n0w = (wid >> 2) << 5;
    int mi = l >> 3;
    int rA = m0 + ((mi & 1) << 3) + (l & 7);
    uint32_t qA0 = swz(rA, mi >> 1);
    int rB = n0w + (((mi >> 1) & 1) << 3) + (l & 7);
    uint32_t qB0 = swz(rB, mi & 1);

    float acc[2][4][4];
#pragma unroll
    for (int i = 0; i < 2; i++)
#pragma unroll
        for (int j = 0; j < 4; j++)
#pragma unroll
            for (int k = 0; k < 4; k++) acc[i][j][k] = 0.f;

    auto load_chunk = [&](int kc, int stage) {
        size_t coff = (size_t)(kc << 5);
        uint32_t st = sbase + (uint32_t)stage*STAGE_BYTES;
        cpa16(st + ph0,         Abase_hi + a0 + coff);
        cpa16(st + 8192 + ph0,  Abase_lo + a0 + coff);
        cpa16(st + ph1,         Abase_hi + a1 + coff);
        cpa16(st + 8192 + ph1,  Abase_lo + a1 + coff);
        cpa16(st + 16384 + ph0, Bbase_hi + a0 + coff);
        cpa16(st + 20480 + ph0, Bbase_lo + a0 + coff);
        cp_commit();
    };

    load_chunk(0, 0);
    load_chunk(1, 1);

    for (int kc = 0; kc < 8; kc++) {
        int stage = kc % 3;
        if (kc < 6) cp_wait<1>(); else cp_wait<0>();
        __syncthreads();
        if (kc + 2 < 8) load_chunk(kc + 2, (kc + 2) % 3);

        uint32_t st = sbase + (uint32_t)stage*STAGE_BYTES;
        uint32_t Ahi = st, Alo = st + 8192, Bhi = st + 16384, Blo = st + 20480;
#pragma unroll
        for (int ks = 0; ks < 2; ks++) {
            uint32_t kx = (uint32_t)(ks << 5);
            uint32_t qa = qA0 ^ kx, qb = qB0 ^ kx;
            uint32_t ah[8], al[8], bbv[8];
            ldsm4(bbv,     Bhi + qb);
            ldsm4(bbv + 4, Bhi + qb + 1024);
            ldsm4(ah,     Ahi + qa);
            ldsm4(ah + 4, Ahi + qa + 1024);
            ldsm4(al,     Alo + qa);
            ldsm4(al + 4, Alo + qa + 1024);
#pragma unroll
            for (int nf = 0; nf < 4; nf++) {
                const uint32_t* bp = bbv + nf*2;
                mma16816(acc[0][nf], ah,     bp);
                mma16816(acc[1][nf], ah + 4, bp);
            }
#pragma unroll
            for (int nf = 0; nf < 4; nf++) {
                const uint32_t* bp = bbv + nf*2;
                mma16816(acc[0][nf], al,     bp);
                mma16816(acc[1][nf], al + 4, bp);
            }
            ldsm4(bbv,     Blo + qb);
            ldsm4(bbv + 4, Blo + qb + 1024);
#pragma unroll
            for (int nf = 0; nf < 4; nf++) {
                const uint32_t* bp = bbv + nf*2;
                mma16816(acc[0][nf], ah,     bp);
                mma16816(acc[1][nf], ah + 4, bp);
            }
        }
    }

    int row0 = m0 + (l >> 2);
    int col0 = n0w + ((l & 3) << 1);
    float* gm = g_m + ((size_t)pos*NTIL + t0)*256 + nq*64;
#pragma unroll
    for (int mf = 0; mf < 2; mf++)
#pragma unroll
        for (int hf = 0; hf < 2; hf++) {
            int r = row0 + mf*16 + hf*8;
            float* rowp = gm + (size_t)r*256;
#pragma unroll
            for (int nf = 0; nf < 4; nf++)
                *(float2*)(rowp + col0 + nf*8) =
                    make_float2(acc[mf][nf][hf*2], acc[mf][nf][hf*2 + 1]);
        }
}

// ---------------- pre2 (+ fused xT) ----------------
__global__ void pre2_kernel(const float* __restrict__ x, float scale) {
    __shared__ float sx[256][33];
    int tid = threadIdx.x, lane = tid & 31, w8 = tid >> 5;
    int p0 = blockIdx.x * 32;
    int b = p0 >> 10, hw0 = p0 & 1023;
#pragma unroll 8
    for (int i = 0; i < 32; i++) {
        int c = i*8 + w8;
        sx[c][lane] = x[(size_t)(b*256 + c)*1024 + hw0 + lane];
    }
    __syncthreads();
#pragma unroll 8
    for (int pl = 0; pl < 32; pl++)
        g_xl[(size_t)(p0 + pl)*256 + tid] = sx[tid][pl];
#pragma unroll
    for (int pp = 0; pp < 4; pp++) {
        int pl = w8*4 + pp;
        int p = p0 + pl;
        float xv[8];
#pragma unroll
        for (int i = 0; i < 8; i++) xv[i] = sx[lane*8 + i][pl];
        float q = 0.f;
#pragma unroll
        for (int i = 0; i < 8; i++) q += xv[i]*xv[i];
        float n2 = warpSum(q);
        float n = sqrtf(fmaxf(n2, EPSF));
        float f = fdivf(atanh_fast(fminf(n, CLIP1)), n) * scale;
        float4 o0 = make_float4(f*xv[0], f*xv[1], f*xv[2], f*xv[3]);
        float4 o1 = make_float4(f*xv[4], f*xv[5], f*xv[6], f*xv[7]);
        float* dst = g_v + (size_t)p*256 + lane*8;
        *(float4*)dst = o0;
        *(float4*)(dst + 4) = o1;
        if (lane == 0) g_q2[p] = f*f*n2;
    }
}

// ---------------- per-pixel s ----------------
__device__ __forceinline__ float s_from_q2(int p) {
    int h = (p >> 5) & 31, w = p & 31;
    float np2 = 0.f;
#pragma unroll
    for (int dy = -1; dy <= 1; dy++)
#pragma unroll
        for (int dx = -1; dx <= 1; dx++) {
            int sh = h + dy, sw = w + dx;
            if ((unsigned)sh < 32u && (unsigned)sw < 32u) np2 += g_q2[p + dy*32 + dx];
        }
    float np = sqrtf(fmaxf(np2, EPSF));
    float th = tanh_fast(np);
    float uf = fdivf(th, np);
    float un = th;
    if (un > MAXN) { uf *= fdivf(MAXN, un); un = MAXN; }
    float lam = fdivf(2.0f, fmaxf(1.0f - un*un, EPSF));
    return lam * uf;
}

// ---------------- output transform + FC + BN partials; writes NORMALIZED h ----------------
__global__ void wino_out(int znoff) {
    __shared__ float ss[16];
    __shared__ float slam[16];
    __shared__ float sld[16];
    __shared__ float sinv[16];
    __shared__ float ybuf[16][260];
    int t = blockIdx.x, co = threadIdx.x;
    int b = t >> 6, tr = (t >> 3) & 7, tc = t & 7;
    int prow = (b << 10) + (4*tr)*32 + 4*tc;
    if (co < 16) {
        int r = co >> 2, c = co & 3;
        ss[co] = s_from_q2(prow + r*32 + c);
    }
    float m[36];
#pragma unroll
    for (int pos = 0; pos < 36; pos++)
        m[pos] = g_m[((size_t)pos*NTIL + t)*256 + co];
    float Z[4][6];
#pragma unroll
    for (int bb = 0; bb < 6; bb++) {
        float in[6] = { m[bb], m[6+bb], m[12+bb], m[18+bb], m[24+bb], m[30+bb] };
        float out[4];
        at6(in, out);
#pragma unroll
        for (int r = 0; r < 4; r++) Z[r][bb] = out[r];
    }
    float zn = g_zn[znoff + co];
    float izn = __fdividef(1.0f, zn);
    float a2 = 2.0f * zn;
    __syncthreads();
#pragma unroll
    for (int r = 0; r < 4; r++) {
        float Y[4];
        at6(Z[r], Y);
#pragma unroll
        for (int c = 0; c < 4; c++) {
            float s = ss[r*4 + c];
            float tt = Y[c] * s * izn;
            float w = tt + sqrtf(fmaf(tt, tt, 1.0f));
            float u = __logf(w);
            float au = a2 * u;
            ybuf[r*4 + c][co] = 0.5f * (__expf(au) - __expf(-au));
        }
    }
    __syncthreads();
    int wd = co >> 5, lid = co & 31;
#pragma unroll
    for (int k = 0; k < 2; k++) {
        int pl = wd*2 + k;
        float q = 0.f;
#pragma unroll
        for (int i = 0; i < 8; i++) {
            float v = ybuf[pl][lid*8 + i];
            q += v*v;
        }
        float tot = warpSum(q);
        float inv = fdivf(1.0f, 1.0f + sqrtf(1.0f + tot));
        float n2 = tot*inv*inv;
        float lam = fdivf(2.0f, fmaxf(1.0f - n2, EPSF));
        if (lid == 0) { slam[pl] = lam*inv; sld[pl] = lam - 1.0f; sinv[pl] = inv; }
    }
    __syncthreads();
    float accm = 0.f;
#pragma unroll
    for (int pl = 0; pl < 16; pl++)
        accm += slam[pl] * ybuf[pl][co];
    g_pm[t*256 + co] = accm;
    if (co == 0) {
        float d = 0.f;
#pragma unroll
        for (int pl = 0; pl < 16; pl++) d += sld[pl];
        g_pd[t] = d;
    }
#pragma unroll
    for (int pl = 0; pl < 16; pl++) {
        int p = prow + (pl >> 2)*32 + (pl & 3);
        g_h[(size_t)p*256 + co] = ybuf[pl][co] * sinv[pl];
    }
}

// ---------------- BN mu: 32-block partial sum + last-block finalize ----------------
__global__ void bnmu_kernel(const float* __restrict__ bias) {
    __shared__ float sb[24];
    __shared__ int slast;
    int c = threadIdx.x;
    float s = 0.f;
    int g0 = blockIdx.x * 32;
    for (int g = 0; g < 32; g++) s += g_pm[(g0 + g)*256 + c];
    g_pm2[blockIdx.x*256 + c] = s;
    __threadfence();
    if (c == 0) slast = (atomicAdd(&g_ctr2, 1) == 31);
    __syncthreads();
    if (!slast) return;
    __threadfence();
    float msum = 0.f;
#pragma unroll
    for (int j = 0; j < 32; j++) msum += g_pm2[j*256 + c];
    float dv = 0.f;
#pragma unroll
    for (int j = 0; j < 4; j++) dv += g_pd[j*256 + c];
    float r1[1] = { dv };
    blockReduceK<1>(r1, sb);
    float den = fmaxf(r1[0], EPSF);
    float m = msum / den;
    float r2[1] = { m*m };
    blockReduceK<1>(r2, sb);
    float nm = sqrtf(fmaxf(r2[0], EPSF));
    float fac = tanh_fast(0.5f * atanh_fast(fminf(nm, CLIP1))) / nm;
    float muc = fac * m;
    g_mu[c] = muc;
    float bc = bias[c];
    float r3[3] = { muc*muc, bc*bc, bc*muc };
    blockReduceK<3>(r3, sb);
    if (c == 0) {
        float mu2 = r3[0], b2 = r3[1], bm = r3[2];
        g_sc[0] = mu2;
        g_sc[1] = 2.0f / fmaxf(1.0f - mu2, EPSF);
        g_sc[2] = b2;
        g_sc[3] = 2.0f / fmaxf(1.0f - b2, EPSF);
        g_sc[4] = bm;
        ((volatile float*)g_sc)[5] = 0.f;
        g_ctr2 = 0;
    }
}

// ---------------- variance partial (normalized input) ----------------
__device__ __forceinline__ float var_pixel(int p, const float* mu8, float mu2) {
    int lid = threadIdx.x & 31;
    const float4* row = (const float4*)(g_h + (size_t)p*256 + lid*8);
    float4 a = row[0], cc = row[1];
    float v[8] = {a.x,a.y,a.z,a.w,cc.x,cc.y,cc.z,cc.w};
    float q1 = 0.f, q2 = 0.f;
#pragma unroll
    for (int j = 0; j < 8; j++) { q1 += v[j]*v[j]; q2 += v[j]*mu8[j]; }
    float xp2 = warpSum(q1);
    float ip  = warpSum(q2);
    float A = 1.0f - 2.0f*ip + mu2;
    float B = 1.0f - xp2;
    float nn = fmaxf(A*A*xp2 - 2.0f*A*B*ip + B*B*mu2, 0.f);
    float den = fmaxf(1.0f - 2.0f*ip + xp2*mu2, EPSF);
    float nr = sqrtf(fmaxf(fdivf(nn, den*den), EPSF));
    float dd = 2.0f * atanh_fast(fminf(nr, CLIP1));
    return dd*dd;
}

// ---------------- shared BN point transform ----------------
__device__ __forceinline__ float bn_point_w(const float* xv, const float* mu8, const float* b8,
                                            float* hc) {
    float mu2 = g_sc[0], lam_mu = g_sc[1], b2 = g_sc[2], lam_b = g_sc[3],
          bm = g_sc[4], rstd = g_sc[5];
    float s0 = 0.f, s1 = 0.f, s2 = 0.f;
#pragma unroll
    for (int i = 0; i < 8; i++) { s0 += xv[i]*xv[i]; s1 += mu8[i]*xv[i]; s2 += b8[i]*xv[i]; }
    float xp2 = warpSum(s0), ip = warpSum(s1), bx = warpSum(s2);
    float A  = 1.0f - 2.0f*ip + xp2;
    float Bc = 1.0f - mu2;
    float den = fmaxf(1.0f - 2.0f*ip + mu2*xp2, EPSF);
    float iden = fdivf(1.0f, den);
    float nd2 = fmaxf(A*A*mu2 - 2.0f*A*Bc*ip + Bc*Bc*xp2, 0.f) * iden * iden;
    float nd = sqrtf(fmaxf(nd2, EPSF));
    float cv = fdivf(2.0f, lam_mu) * fdivf(atanh_fast(fminf(nd, CLIP1)), nd);
    float uw = cv * (Bc*bx - A*bm) * iden;
    float vw = cv * (A*mu2 - Bc*ip) * iden;
    float av  = -uw*mu2 - vw - 2.0f*bm*vw;
    float bv2 = -vw*b2 + uw;
    float idgy = fdivf(2.0f, fmaxf(1.0f - 2.0f*bm + b2*mu2, EPSF));
    float fac = fdivf(lam_mu, lam_b) * rstd;
    float uc[8];
    float t0 = 0.f, t1 = 0.f;
#pragma unroll
    for (int i = 0; i < 8; i++) {
        float vc = cv * (Bc*xv[i] - A*mu8[i]) * iden;
        uc[i] = (vc + (av*b8[i] - bv2*mu8[i]) * idgy) * fac;
        t0 += uc[i]*uc[i];
        t1 += b8[i]*uc[i];
    }
    float u2 = warpSum(t0), bu = warpSum(t1);
    float nu = sqrtf(fmaxf(u2, EPSF));
    float tf = fdivf(tanh_fast(0.5f * lam_b * nu), nu);
    float s2m = tf*tf*u2;
    float bs  = tf*bu;
    float A3 = 1.0f + 2.0f*bs + s2m, B3 = 1.0f - b2;
    float iden3 = fdivf(1.0f, fmaxf(1.0f + 2.0f*bs + b2*s2m, EPSF));
#pragma unroll
    for (int i = 0; i < 8; i++) hc[i] = (A3*b8[i] + B3*tf*uc[i]) * iden3;
    float nh2 = fmaxf(A3*A3*b2 + 2.0f*A3*B3*bs + B3*B3*s2m, 0.f) * iden3 * iden3;
    float nh = sqrtf(fmaxf(nh2, EPSF));
    if (nh > MAXN) {
        float q = fdivf(MAXN, nh);
#pragma unroll
        for (int i = 0; i < 8; i++) hc[i] *= q;
        nh = MAXN;
    }
    return nh;
}

// ---------------- FUSED variance + BN apply + hrelu + pre-for-conv2 ----------------
__global__ void bnva_kernel(const float* __restrict__ bias, const float* __restrict__ weight,
                            float scale) {
    __shared__ float sv[8];
    __shared__ int slast;
    int wid = threadIdx.x >> 5, lid = threadIdx.x & 31;
    int p0 = blockIdx.x * 64;
    float mu8[8];
#pragma unroll
    for (int j = 0; j < 8; j++) mu8[j] = g_mu[lid*8 + j];
    float mu2 = g_sc[0];
    float acc = 0.f;
    for (int i = 0; i < 8; i++)
        acc += var_pixel(p0 + wid*8 + i, mu8, mu2);
    if (lid == 0) sv[wid] = acc;
    __syncthreads();
    if (threadIdx.x == 0) {
        float s = 0.f;
        for (int w = 0; w < 8; w++) s += sv[w];
        g_pv[blockIdx.x] = s;
        __threadfence();
        slast = (atomicAdd(&g_ctr, 1) == 255);
    }
    __syncthreads();
    if (slast) {
        float v = g_pv[threadIdx.x];
        __shared__ float sb[8];
        float r[1] = { v };
        blockReduceK<1>(r, sb);
        if (threadIdx.x == 0) {
            float var = r[0] / 16384.0f;
            g_ctr = 0;
            __threadfence();
            ((volatile float*)g_sc)[5] = sqrtf(weight[0] / fmaxf(var, EPSF));
        }
    }
    if (threadIdx.x == 0) {
        volatile float* vs = g_sc;
        while (vs[5] == 0.f) { }
    }
    __syncthreads();
    float b8[8];
#pragma unroll
    for (int j = 0; j < 8; j++) b8[j] = bias[lid*8 + j];
    for (int i = 0; i < 8; i++) {
        int p = p0 + wid*8 + i;
        const float4* row = (const float4*)(g_h + (size_t)p*256 + lid*8);
        float4 a = row[0], cc = row[1];
        float xv[8] = {a.x,a.y,a.z,a.w,cc.x,cc.y,cc.z,cc.w};
        float hc[8];
        float nh = bn_point_w(xv, mu8, b8, hc);
        float lf = fdivf(atanh_fast(fminf(nh, CLIP1)), nh);
        float rc[8];
        float q = 0.f;
#pragma unroll
        for (int k = 0; k < 8; k++) { rc[k] = fmaxf(lf*hc[k], 0.f); q += rc[k]*rc[k]; }
        float rs = warpSum(q);
        float nr = sqrtf(fmaxf(rs, EPSF));
        float ef = fdivf(tanh_fast(nr), nr);
        float nhr = sqrtf(fmaxf(ef*ef*rs, EPSF));
        float adj = 1.0f;
        if (nhr > MAXN) { adj = fdivf(MAXN, nhr); nhr = MAXN; }
        float f3 = fdivf(atanh_fast(fminf(nhr, CLIP1)), nhr) * scale;
        float g = f3 * ef * adj;
        float4 o0 = make_float4(g*rc[0], g*rc[1], g*rc[2], g*rc[3]);
        float4 o1 = make_float4(g*rc[4], g*rc[5], g*rc[6], g*rc[7]);
        float* dst = g_v + (size_t)p*256 + lid*8;
        *(float4*)dst = o0;
        *(float4*)(dst + 4) = o1;
        if (lid == 0) g_q2[p] = f3*f3*nhr*nhr;
    }
}

// ---------------- FUSED variance + BN2 apply + residual + hrelu + NCHW out ----------------
__global__ void bnvf_kernel(const float* __restrict__ bias, const float* __restrict__ weight,
                            float* __restrict__ out) {
    __shared__ float so[256][33];
    __shared__ float sv[8];
    __shared__ int slast;
    int tid = threadIdx.x, lane = tid & 31, w8 = tid >> 5;
    int p0 = blockIdx.x * 32;
    int b = p0 >> 10, hw0 = p0 & 1023;
    float mu8[8], b8[8];
#pragma unroll
    for (int j = 0; j < 8; j++) { mu8[j] = g_mu[lane*8 + j]; b8[j] = bias[lane*8 + j]; }
    float mu2 = g_sc[0];
    float acc = 0.f;
    for (int i = 0; i < 4; i++)
        acc += var_pixel(p0 + w8*4 + i, mu8, mu2);
    if (lane == 0) sv[w8] = acc;
    __syncthreads();
    if (tid == 0) {
        float s = 0.f;
        for (int w = 0; w < 8; w++) s += sv[w];
        g_pv[blockIdx.x] = s;
        __threadfence();
        slast = (atomicAdd(&g_ctr, 1) == 511);
    }
    __syncthreads();
    if (slast) {
        float v = g_pv[tid] + g_pv[tid + 256];
        __shared__ float sb[8];
        float r[1] = { v };
        blockReduceK<1>(r, sb);
        if (tid == 0) {
            float var = r[0] / 16384.0f;
            g_ctr = 0;
            __threadfence();
            ((volatile float*)g_sc)[5] = sqrtf(weight[0] / fmaxf(var, EPSF));
        }
    }
    if (tid == 0) {
        volatile float* vs = g_sc;
        while (vs[5] == 0.f) { }
    }
    __syncthreads();
#pragma unroll
    for (int pp = 0; pp < 4; pp++) {
        int pl = w8*4 + pp;
        int p = p0 + pl;
        const float4* row = (const float4*)(g_h + (size_t)p*256 + lane*8);
        float4 a = row[0], cc = row[1];
        float xv[8] = {a.x,a.y,a.z,a.w,cc.x,cc.y,cc.z,cc.w};
        float hc[8];
        float nh = bn_point_w(xv, mu8, b8, hc);
        const float4* rrow = (const float4*)(g_xl + (size_t)p*256 + lane*8);
        float4 r0 = rrow[0], r1 = rrow[1];
        float res[8] = {r0.x,r0.y,r0.z,r0.w,r1.x,r1.y,r1.z,r1.w};
        float q1 = 0.f, q2 = 0.f;
#pragma unroll
        for (int i = 0; i < 8; i++) { q1 += res[i]*res[i]; q2 += hc[i]*res[i]; }
        float y2 = warpSum(q1), xy = warpSum(q2);
        float x2 = nh*nh;
        float A4 = 1.0f + 2.0f*xy + y2, B4 = 1.0f - x2;
        float iden4 = fdivf(1.0f, fmaxf(1.0f + 2.0f*xy + x2*y2, EPSF));
        float hm[8];
#pragma unroll
        for (int i = 0; i < 8; i++) hm[i] = (A4*hc[i] + B4*res[i]) * iden4;
        float nm2 = fmaxf(A4*A4*x2 + 2.0f*A4*B4*xy + B4*B4*y2, 0.f) * iden4 * iden4;
        float nmv = sqrtf(fmaxf(nm2, EPSF));
        float lf = fdivf(atanh_fast(fminf(nmv, CLIP1)), nmv);
        float rc[8];
        float q = 0.f;
#pragma unroll
        for (int i = 0; i < 8; i++) { rc[i] = fmaxf(lf*hm[i], 0.f); q += rc[i]*rc[i]; }
        float rs = warpSum(q);
        float nr = sqrtf(fmaxf(rs, EPSF));
        float ef = fdivf(tanh_fast(nr), nr);
        float nhr = sqrtf(fmaxf(ef*ef*rs, EPSF));
        float adj = (nhr > MAXN) ? fdivf(MAXN, nhr) : 1.0f;
#pragma unroll
        for (int i = 0; i < 8; i++) so[lane*8 + i][pl] = ef * adj * rc[i];
    }
    __syncthreads();
#pragma unroll 8
    for (int i = 0; i < 32; i++) {
        int c = i*8 + w8;
        out[(size_t)(b*256 + c)*1024 + hw0 + lane] = so[c][lane];
    }
}

// ---------------- launcher ----------------
extern "C" void kernel_launch(void* const* d_in, const int* in_sizes, int n_in,
                              void* d_out, int out_size) {
    const float* x  = (const float*)d_in[0];
    const float* z1 = (const float*)d_in[1];
    const float* z2 = (const float*)d_in[2];
    const float* w1 = (const float*)d_in[3];
    const float* b1 = (const float*)d_in[4];
    const float* w2 = (const float*)d_in[5];
    const float* b2 = (const float*)d_in[6];
    float* out = (float*)d_out;

    // scale = Beta(1152, 0.5) / Beta(128, 0.5)
    double lg = lgamma(1152.0) - lgamma(1152.5) - lgamma(128.0) + lgamma(128.5);
    float scale = (float)exp(lg);

    static int smem_set = 0;
    if (!smem_set) {
        cudaFuncSetAttribute(wino_gemm, cudaFuncAttributeMaxDynamicSharedMemorySize, CONV_SMEM);
        smem_set = 1;
    }

    dim3 ggrid(8, 4, 36);

    wino_u<<<dim3(256, 2), 256>>>(z1, z2);       // 0
    pre2_kernel<<<PNUM/32, 256>>>(x, scale);     // 1
    wino_in<<<NTIL, 256>>>();                    // 2
    wino_gemm<<<ggrid, 256, CONV_SMEM>>>(0);     // 3  <- ncu capture target
    wino_out<<<NTIL, 256>>>(0);

    bnmu_kernel<<<32, 256>>>(b1);
    bnva_kernel<<<256, 256>>>(b1, w1, scale);

    wino_in<<<NTIL, 256>>>();
    wino_gemm<<<ggrid, 256, CONV_SMEM>>>(1);
    wino_out<<<NTIL, 256>>>(256);

    bnmu_kernel<<<32, 256>>>(b2);
    bnvf_kernel<<<512, 256>>>(b2, w2, out);
}